// round 5
// baseline (speedup 1.0000x reference)
#include <cuda_runtime.h>
#include <math.h>

// Problem constants
#define BB 2
#define SS 128
#define DD 256
#define NH 8
#define HD 32
#define MTOT (BB*SS*SS)      // 32768 rows
#define QKVN 768

// Scratch (allocation-free rule: __device__ globals)
__device__ float g_x[MTOT * DD];       // layernormed input
__device__ float g_qkv[MTOT * QKVN];   // qkv (rotary already applied to q,k head 0)
__device__ float g_att[MTOT * DD];     // attention output
__device__ unsigned char g_mask[32768];  // normalized mask
__device__ int g_mask_kind;            // 0=uint8, 1=int32, 2=float32

// ---------------------------------------------------------------------------
// Mask dtype sniffing: scan FIRST 32768 bytes only (safe for 1/4-byte elems).
// uint8 mask: nonzero bytes appear at offset%4==1 with prob ~1.
// int32 0/1:  nonzero bytes only at offset%4==0.
// float32 0/1 (1.0f = 00 00 80 3f): nonzero only at offset%4 in {2,3}.
// ---------------------------------------------------------------------------
__global__ __launch_bounds__(256)
void detect_mask_kernel(const unsigned char* __restrict__ m)
{
    __shared__ int fa, fb;
    if (threadIdx.x == 0) { fa = 0; fb = 0; }
    __syncthreads();
    for (int i = threadIdx.x; i < 32768; i += 256) {
        unsigned char v = m[i];
        if (v) {
            int r = i & 3;
            if (r == 1) fa = 1;
            else if (r == 0) fb = 1;
        }
    }
    __syncthreads();
    if (threadIdx.x == 0) g_mask_kind = fa ? 0 : (fb ? 1 : 2);
}

__global__ __launch_bounds__(256)
void conv_mask_kernel(const unsigned char* __restrict__ m)
{
    int i = blockIdx.x * 256 + threadIdx.x;   // 32768 threads
    int kind = g_mask_kind;
    unsigned char v;
    if (kind == 0)      v = m[i] ? 1 : 0;
    else if (kind == 1) v = ((const int*)m)[i] ? 1 : 0;
    else                v = (((const float*)m)[i] != 0.f) ? 1 : 0;
    g_mask[i] = v;
}

// ---------------------------------------------------------------------------
// LayerNorm: one block per row of 256
// ---------------------------------------------------------------------------
__global__ __launch_bounds__(256)
void ln_kernel(const float* __restrict__ in,
               const float* __restrict__ gamma,
               const float* __restrict__ beta,
               float* __restrict__ out)
{
    int row = blockIdx.x;
    int t = threadIdx.x;
    float v = in[(size_t)row * DD + t];
    float s = v, s2 = v * v;
    #pragma unroll
    for (int o = 16; o > 0; o >>= 1) {
        s  += __shfl_xor_sync(0xffffffffu, s,  o);
        s2 += __shfl_xor_sync(0xffffffffu, s2, o);
    }
    __shared__ float ws[8], ws2[8];
    int w = t >> 5, l = t & 31;
    if (l == 0) { ws[w] = s; ws2[w] = s2; }
    __syncthreads();
    float tot = 0.f, tot2 = 0.f;
    #pragma unroll
    for (int i = 0; i < 8; i++) { tot += ws[i]; tot2 += ws2[i]; }
    float mu  = tot * (1.f / 256.f);
    float var = tot2 * (1.f / 256.f) - mu * mu;
    float r   = rsqrtf(var + 1e-5f);
    out[(size_t)row * DD + t] = (v - mu) * r * gamma[t] + beta[t];
}

// ---------------------------------------------------------------------------
// NT GEMM: C[m,n] = sum_k A[m,k] * W[n,k].  BM=128, BN=64, BK=16, 256 threads,
// thread tile 8x4.  Optional fused axial rotary on q/k head 0 in the epilogue.
// ---------------------------------------------------------------------------
template<bool DO_ROT>
__global__ __launch_bounds__(256)
void gemm_nt_kernel(const float* __restrict__ A,
                    const float* __restrict__ W,
                    float* __restrict__ C, int N)
{
    const int K = 256;
    __shared__ float As[16][128];
    __shared__ float Bs[16][64];

    int tid = threadIdx.x;
    int tx = tid & 15;
    int ty = tid >> 4;
    int m0 = blockIdx.y * 128;
    int n0 = blockIdx.x * 64;

    float acc[8][4];
    #pragma unroll
    for (int i = 0; i < 8; i++)
        #pragma unroll
        for (int j = 0; j < 4; j++) acc[i][j] = 0.f;

    int lRow = tid >> 2;
    int lC4  = tid & 3;

    for (int k0 = 0; k0 < K; k0 += 16) {
        #pragma unroll
        for (int it = 0; it < 2; it++) {
            int row = lRow + it * 64;
            float4 a = *(const float4*)&A[(size_t)(m0 + row) * K + k0 + lC4 * 4];
            As[lC4 * 4 + 0][row] = a.x;
            As[lC4 * 4 + 1][row] = a.y;
            As[lC4 * 4 + 2][row] = a.z;
            As[lC4 * 4 + 3][row] = a.w;
        }
        {
            float4 b = *(const float4*)&W[(size_t)(n0 + lRow) * K + k0 + lC4 * 4];
            Bs[lC4 * 4 + 0][lRow] = b.x;
            Bs[lC4 * 4 + 1][lRow] = b.y;
            Bs[lC4 * 4 + 2][lRow] = b.z;
            Bs[lC4 * 4 + 3][lRow] = b.w;
        }
        __syncthreads();
        #pragma unroll
        for (int kk = 0; kk < 16; kk++) {
            float4 a0 = *(const float4*)&As[kk][ty * 8];
            float4 a1 = *(const float4*)&As[kk][ty * 8 + 4];
            float4 b0 = *(const float4*)&Bs[kk][tx * 4];
            float av[8] = {a0.x, a0.y, a0.z, a0.w, a1.x, a1.y, a1.z, a1.w};
            float bv[4] = {b0.x, b0.y, b0.z, b0.w};
            #pragma unroll
            for (int i = 0; i < 8; i++)
                #pragma unroll
                for (int j = 0; j < 4; j++)
                    acc[i][j] += av[i] * bv[j];
        }
        __syncthreads();
    }

    if (DO_ROT) {
        bool doRot = (tx < 8) && (n0 == 0 || n0 == 256);
        if (doRot) {
            int p0 = tx * 2;
            #pragma unroll
            for (int i = 0; i < 8; i++) {
                int m  = m0 + ty * 8 + i;
                int xx = (m >> 7) & 127;
                int yy = m & 127;
                #pragma unroll
                for (int pr = 0; pr < 2; pr++) {
                    int p = p0 + pr;
                    float pos  = (p < 8) ? (float)xx : (float)yy;
                    float tpos = (2.f * pos - 127.f) * (1.f / 127.f);
                    float invf = __expf(-(float)(p & 7) * 1.1512925464970228f);
                    float th = tpos * invf;
                    float sn, cs;
                    __sincosf(th, &sn, &cs);
                    float e0 = acc[i][2 * pr], e1 = acc[i][2 * pr + 1];
                    acc[i][2 * pr]     = e0 * cs - e1 * sn;
                    acc[i][2 * pr + 1] = e1 * cs + e0 * sn;
                }
            }
        }
    }

    #pragma unroll
    for (int i = 0; i < 8; i++) {
        int m = m0 + ty * 8 + i;
        float4 v = make_float4(acc[i][0], acc[i][1], acc[i][2], acc[i][3]);
        *(float4*)&C[(size_t)m * N + n0 + tx * 4] = v;
    }
}

// ---------------------------------------------------------------------------
// Attention: one block per (head, x, batch). 128 threads, thread t = q row.
// ---------------------------------------------------------------------------
__global__ __launch_bounds__(128)
void attn_kernel(const float* __restrict__ qkv,
                 float* __restrict__ out)
{
    int h  = blockIdx.x;
    int xx = blockIdx.y;
    int b  = blockIdx.z;
    int t  = threadIdx.x;

    __shared__ float ks[128][36];
    __shared__ float vs[128][36];
    __shared__ float msk[128];

    int rowBase = b * (SS * SS) + xx * SS;

    const float* kbase = qkv + (size_t)rowBase * QKVN + 256 + h * HD;
    const float* vbase = qkv + (size_t)rowBase * QKVN + 512 + h * HD;
    const float* qbase = qkv + (size_t)(rowBase + t) * QKVN + h * HD;

    #pragma unroll
    for (int d4 = 0; d4 < 8; d4++) {
        float4 kv = *(const float4*)&kbase[(size_t)t * QKVN + d4 * 4];
        *(float4*)&ks[t][d4 * 4] = kv;
        float4 vv = *(const float4*)&vbase[(size_t)t * QKVN + d4 * 4];
        *(float4*)&vs[t][d4 * 4] = vv;
    }
    msk[t] = g_mask[rowBase + t] ? 1.f : 0.f;

    float q[32];
    #pragma unroll
    for (int d4 = 0; d4 < 8; d4++) {
        float4 qq = *(const float4*)&qbase[d4 * 4];
        q[d4 * 4 + 0] = qq.x; q[d4 * 4 + 1] = qq.y;
        q[d4 * 4 + 2] = qq.z; q[d4 * 4 + 3] = qq.w;
    }
    __syncthreads();

    float o[32];
    #pragma unroll
    for (int d = 0; d < 32; d++) o[d] = 0.f;
    float mx = -3e38f, l = 0.f;

    for (int j = 0; j < 128; j++) {
        float s = 0.f;
        #pragma unroll
        for (int d4 = 0; d4 < 8; d4++) {
            float4 kv = *(const float4*)&ks[j][d4 * 4];
            s += q[d4*4+0]*kv.x + q[d4*4+1]*kv.y + q[d4*4+2]*kv.z + q[d4*4+3]*kv.w;
        }
        s *= 0.17677669529663687f;
        if (msk[j] != 0.f) s = -1e9f;

        if (s <= mx) {
            float w = __expf(s - mx);
            l += w;
            #pragma unroll
            for (int d4 = 0; d4 < 8; d4++) {
                float4 vv = *(const float4*)&vs[j][d4 * 4];
                o[d4*4+0] += w * vv.x; o[d4*4+1] += w * vv.y;
                o[d4*4+2] += w * vv.z; o[d4*4+3] += w * vv.w;
            }
        } else {
            float corr = __expf(mx - s);
            l = l * corr + 1.f;
            #pragma unroll
            for (int d4 = 0; d4 < 8; d4++) {
                float4 vv = *(const float4*)&vs[j][d4 * 4];
                o[d4*4+0] = o[d4*4+0] * corr + vv.x;
                o[d4*4+1] = o[d4*4+1] * corr + vv.y;
                o[d4*4+2] = o[d4*4+2] * corr + vv.z;
                o[d4*4+3] = o[d4*4+3] * corr + vv.w;
            }
            mx = s;
        }
    }

    float rl = 1.f / l;
    float* obase = out + (size_t)(rowBase + t) * DD + h * HD;
    #pragma unroll
    for (int d4 = 0; d4 < 8; d4++) {
        float4 vv = make_float4(o[d4*4+0]*rl, o[d4*4+1]*rl, o[d4*4+2]*rl, o[d4*4+3]*rl);
        *(float4*)&obase[d4 * 4] = vv;
    }
}

// ---------------------------------------------------------------------------
extern "C" void kernel_launch(void* const* d_in, const int* in_sizes, int n_in,
                              void* d_out, int out_size)
{
    const float* pair_act = nullptr;
    const unsigned char* pair_mask = nullptr;
    const float* ln_gamma = nullptr;
    const float* ln_beta  = nullptr;
    const float* Wqkv = nullptr;
    const float* Wout = nullptr;

    for (int i = 0; i < n_in; i++) {
        int sz = in_sizes[i];
        if      (sz == 8388608) pair_act  = (const float*)d_in[i];
        else if (sz == 32768)   pair_mask = (const unsigned char*)d_in[i];
        else if (sz == 196608)  Wqkv      = (const float*)d_in[i];
        else if (sz == 65536)   Wout      = (const float*)d_in[i];
        else if (sz == 256) {
            if (!ln_gamma) ln_gamma = (const float*)d_in[i];
            else           ln_beta  = (const float*)d_in[i];
        }
    }

    float* out = (float*)d_out;

    void *px, *pqkv, *patt;
    cudaGetSymbolAddress(&px,   g_x);
    cudaGetSymbolAddress(&pqkv, g_qkv);
    cudaGetSymbolAddress(&patt, g_att);

    detect_mask_kernel<<<1, 256>>>(pair_mask);
    conv_mask_kernel<<<128, 256>>>(pair_mask);

    ln_kernel<<<MTOT, 256>>>(pair_act, ln_gamma, ln_beta, (float*)px);

    gemm_nt_kernel<true><<<dim3(QKVN / 64, MTOT / 128), 256>>>(
        (const float*)px, Wqkv, (float*)pqkv, QKVN);

    attn_kernel<<<dim3(NH, SS, BB), 128>>>(
        (const float*)pqkv, (float*)patt);

    gemm_nt_kernel<false><<<dim3(DD / 64, MTOT / 128), 256>>>(
        (const float*)patt, Wout, out, DD);
}

// round 7
// speedup vs baseline: 1.8736x; 1.8736x over previous
#include <cuda_runtime.h>
#include <cuda_bf16.h>
#include <cstdint>
#include <math.h>

// Problem constants
#define BB 2
#define SS 128
#define DD 256
#define NH 8
#define HD 32
#define MTOT (BB*SS*SS)      // 32768 rows
#define QKVN 768

// Scratch (allocation-free rule: __device__ globals)
__device__ __nv_bfloat16 g_x_hi[MTOT * DD];
__device__ __nv_bfloat16 g_x_lo[MTOT * DD];
__device__ float         g_qkv[MTOT * QKVN];
__device__ __nv_bfloat16 g_att_hi[MTOT * DD];
__device__ __nv_bfloat16 g_att_lo[MTOT * DD];
__device__ __nv_bfloat16 g_wq_hi[QKVN * DD];
__device__ __nv_bfloat16 g_wq_lo[QKVN * DD];
__device__ __nv_bfloat16 g_wo_hi[DD * DD];
__device__ __nv_bfloat16 g_wo_lo[DD * DD];
__device__ unsigned char g_mask[32768];
__device__ int g_mask_kind;

// ===========================================================================
// Helpers
// ===========================================================================
__device__ __forceinline__ uint32_t smem_u32(const void* p) {
    uint32_t a;
    asm("{ .reg .u64 t; cvta.to.shared.u64 t, %1; cvt.u32.u64 %0, t; }" : "=r"(a) : "l"(p));
    return a;
}
__device__ __forceinline__ uint32_t swz(uint32_t o) {       // SW128 swizzle
    return o ^ ((o >> 3) & 0x70);
}
__device__ __forceinline__ void bf16_split(float x, __nv_bfloat16& h, __nv_bfloat16& l) {
    h = __float2bfloat16(x);
    l = __float2bfloat16(x - __bfloat162float(h));
}
__device__ __forceinline__ void mma16816(float* c, const uint32_t* a, const uint32_t* b) {
    asm volatile("mma.sync.aligned.m16n8k16.row.col.f32.bf16.bf16.f32 "
        "{%0,%1,%2,%3}, {%4,%5,%6,%7}, {%8,%9}, {%0,%1,%2,%3};"
        : "+f"(c[0]), "+f"(c[1]), "+f"(c[2]), "+f"(c[3])
        : "r"(a[0]), "r"(a[1]), "r"(a[2]), "r"(a[3]), "r"(b[0]), "r"(b[1]));
}
#define LDSM_X4(r, addr) \
    asm volatile("ldmatrix.sync.aligned.m8n8.x4.shared.b16 {%0,%1,%2,%3}, [%4];" \
        : "=r"((r)[0]), "=r"((r)[1]), "=r"((r)[2]), "=r"((r)[3]) : "r"(addr))

// ===========================================================================
// Mask normalization (dtype-sniffing)
// ===========================================================================
__global__ __launch_bounds__(256)
void detect_mask_kernel(const unsigned char* __restrict__ m)
{
    __shared__ int fa, fb;
    if (threadIdx.x == 0) { fa = 0; fb = 0; }
    __syncthreads();
    for (int i = threadIdx.x; i < 32768; i += 256) {
        unsigned char v = m[i];
        if (v) { int r = i & 3; if (r == 1) fa = 1; else if (r == 0) fb = 1; }
    }
    __syncthreads();
    if (threadIdx.x == 0) g_mask_kind = fa ? 0 : (fb ? 1 : 2);
}

__global__ __launch_bounds__(256)
void conv_mask_kernel(const unsigned char* __restrict__ m)
{
    int i = blockIdx.x * 256 + threadIdx.x;
    int kind = g_mask_kind;
    unsigned char v;
    if (kind == 0)      v = m[i] ? 1 : 0;
    else if (kind == 1) v = ((const int*)m)[i] ? 1 : 0;
    else                v = (((const float*)m)[i] != 0.f) ? 1 : 0;
    g_mask[i] = v;
}

// ===========================================================================
// Weight split: fp32 -> bf16 hi/lo
// ===========================================================================
__global__ __launch_bounds__(256)
void convw_kernel(const float* __restrict__ w, int n,
                  __nv_bfloat16* __restrict__ hi, __nv_bfloat16* __restrict__ lo)
{
    int i = blockIdx.x * 256 + threadIdx.x;
    if (i < n) {
        __nv_bfloat16 h, l;
        bf16_split(w[i], h, l);
        hi[i] = h; lo[i] = l;
    }
}

// ===========================================================================
// LayerNorm: one block per row of 256; writes bf16 hi/lo split
// ===========================================================================
__global__ __launch_bounds__(256)
void ln_kernel(const float* __restrict__ in,
               const float* __restrict__ gamma,
               const float* __restrict__ beta,
               __nv_bfloat16* __restrict__ oh,
               __nv_bfloat16* __restrict__ ol)
{
    int row = blockIdx.x;
    int t = threadIdx.x;
    float v = in[(size_t)row * DD + t];
    float s = v, s2 = v * v;
    #pragma unroll
    for (int o = 16; o > 0; o >>= 1) {
        s  += __shfl_xor_sync(0xffffffffu, s,  o);
        s2 += __shfl_xor_sync(0xffffffffu, s2, o);
    }
    __shared__ float ws[8], ws2[8];
    int w = t >> 5, l = t & 31;
    if (l == 0) { ws[w] = s; ws2[w] = s2; }
    __syncthreads();
    float tot = 0.f, tot2 = 0.f;
    #pragma unroll
    for (int i = 0; i < 8; i++) { tot += ws[i]; tot2 += ws2[i]; }
    float mu  = tot * (1.f / 256.f);
    float var = tot2 * (1.f / 256.f) - mu * mu;
    float r   = rsqrtf(var + 1e-5f);
    float y = (v - mu) * r * gamma[t] + beta[t];
    __nv_bfloat16 h, lo2;
    bf16_split(y, h, lo2);
    oh[(size_t)row * DD + t] = h;
    ol[(size_t)row * DD + t] = lo2;
}

// ===========================================================================
// bf16 3-term NT GEMM via mma.sync (base sm_103-safe tensor path).
// C[m,n] = sum_k A[m,k]*W[n,k] in fp32-equivalent precision.
// BM=128, BN=128, BK=64; 256 threads = warps 4(m) x 2(n); warp tile 32x64.
// K=256 fixed. Optional fused axial rotary (q/k head 0) for the QKV GEMM.
// ===========================================================================
#define OFF_AH 0
#define OFF_AL 16384
#define OFF_BH 32768
#define OFF_BL 49152
#define GEMM_SMEM (65536 + 1024)

template<int N, bool DO_ROT>
__global__ void __launch_bounds__(256)
gemm_bf16_kernel(const __nv_bfloat16* __restrict__ Ah,
                 const __nv_bfloat16* __restrict__ Al,
                 const __nv_bfloat16* __restrict__ Bh,
                 const __nv_bfloat16* __restrict__ Bl,
                 float* __restrict__ C)
{
    extern __shared__ char smem_raw[];
    char* smem = (char*)(((uintptr_t)smem_raw + 1023) & ~(uintptr_t)1023);
    uint32_t sb = smem_u32(smem);

    const int tid = threadIdx.x;
    const int lane = tid & 31;
    const int wid = tid >> 5;
    const int wm = wid & 3;        // 0..3 -> m offset 32*wm
    const int wn = wid >> 2;       // 0..1 -> n offset 64*wn
    const int m0 = blockIdx.y * 128;
    const int n0 = blockIdx.x * 128;

    float acc[2][8][4];
    #pragma unroll
    for (int i = 0; i < 2; i++)
        #pragma unroll
        for (int j = 0; j < 8; j++)
            #pragma unroll
            for (int k = 0; k < 4; k++) acc[i][j][k] = 0.f;

    // ldmatrix lane addressing (precompute invariants)
    const int aRow = (lane & 15);
    const int aHalf = (lane >> 4) * 16;
    const int bRow = ((lane >> 4) << 3) + (lane & 7);
    const int bHalf = ((lane >> 3) & 1) * 16;

    for (int chunk = 0; chunk < 4; chunk++) {
        int k0 = chunk * 64;
        // ---- load chunk to smem (swizzled) ----
        #pragma unroll
        for (int s = 0; s < 4; s++) {
            int idx = s * 256 + tid;
            int row = idx >> 3;
            int cs  = idx & 7;
            uint32_t so = swz((uint32_t)(row * 128 + cs * 16));
            size_t ga = (size_t)(m0 + row) * 256 + k0 + cs * 8;
            size_t gb = (size_t)(n0 + row) * 256 + k0 + cs * 8;
            *(uint4*)(smem + OFF_AH + so) = *(const uint4*)(Ah + ga);
            *(uint4*)(smem + OFF_AL + so) = *(const uint4*)(Al + ga);
            *(uint4*)(smem + OFF_BH + so) = *(const uint4*)(Bh + gb);
            *(uint4*)(smem + OFF_BL + so) = *(const uint4*)(Bl + gb);
        }
        __syncthreads();

        // ---- compute: 4 k16 steps ----
        #pragma unroll
        for (int kk = 0; kk < 4; kk++) {
            int kb = kk * 32;
            uint32_t ah[2][4], al[2][4];
            #pragma unroll
            for (int mt = 0; mt < 2; mt++) {
                uint32_t o = swz((uint32_t)((wm * 32 + mt * 16 + aRow) * 128 + kb + aHalf));
                LDSM_X4(ah[mt], sb + OFF_AH + o);
                LDSM_X4(al[mt], sb + OFF_AL + o);
            }
            #pragma unroll
            for (int p = 0; p < 4; p++) {
                uint32_t bo = swz((uint32_t)((wn * 64 + p * 16 + bRow) * 128 + kb + bHalf));
                uint32_t bh[4], bl[4];
                LDSM_X4(bh, sb + OFF_BH + bo);
                LDSM_X4(bl, sb + OFF_BL + bo);
                #pragma unroll
                for (int t2 = 0; t2 < 2; t2++) {
                    int nt = p * 2 + t2;
                    #pragma unroll
                    for (int mt = 0; mt < 2; mt++) {
                        mma16816(acc[mt][nt], ah[mt], &bh[t2 * 2]);
                        mma16816(acc[mt][nt], ah[mt], &bl[t2 * 2]);
                        mma16816(acc[mt][nt], al[mt], &bh[t2 * 2]);
                    }
                }
            }
        }
        __syncthreads();
    }

    // ---- epilogue: optional rotary + fp32 store ----
    #pragma unroll
    for (int mt = 0; mt < 2; mt++) {
        int row0 = m0 + wm * 32 + mt * 16 + (lane >> 2);
        #pragma unroll
        for (int nt = 0; nt < 8; nt++) {
            int colg = n0 + wn * 64 + nt * 8 + (lane & 3) * 2;
            float d0 = acc[mt][nt][0], d1 = acc[mt][nt][1];
            float d2 = acc[mt][nt][2], d3 = acc[mt][nt][3];
            if (DO_ROT) {
                bool doRot = (colg < 32) || (colg >= 256 && colg < 288);
                if (doRot) {
                    int p = (colg & 31) >> 1;
                    float invf = __expf(-(float)(p & 7) * 1.1512925464970228f);
                    #pragma unroll
                    for (int rr = 0; rr < 2; rr++) {
                        int m = row0 + rr * 8;
                        int xx = (m >> 7) & 127;
                        int yy = m & 127;
                        float pos  = (p < 8) ? (float)xx : (float)yy;
                        float tpos = (2.f * pos - 127.f) * (1.f / 127.f);
                        float sn, cs;
                        __sincosf(tpos * invf, &sn, &cs);
                        if (rr == 0) {
                            float e0 = d0, e1 = d1;
                            d0 = e0 * cs - e1 * sn;
                            d1 = e1 * cs + e0 * sn;
                        } else {
                            float e0 = d2, e1 = d3;
                            d2 = e0 * cs - e1 * sn;
                            d3 = e1 * cs + e0 * sn;
                        }
                    }
                }
            }
            *(float2*)&C[(size_t)row0 * N + colg]       = make_float2(d0, d1);
            *(float2*)&C[(size_t)(row0 + 8) * N + colg] = make_float2(d2, d3);
        }
    }
}

// ===========================================================================
// Attention: one block per (head, x, batch). 128 threads, thread t = q row.
// Writes bf16 hi/lo split for the out-GEMM.
// ===========================================================================
__global__ __launch_bounds__(128)
void attn_kernel(const float* __restrict__ qkv,
                 __nv_bfloat16* __restrict__ oh,
                 __nv_bfloat16* __restrict__ ol)
{
    int h  = blockIdx.x;
    int xx = blockIdx.y;
    int b  = blockIdx.z;
    int t  = threadIdx.x;

    __shared__ float ks[128][36];
    __shared__ float vs[128][36];
    __shared__ float msk[128];

    int rowBase = b * (SS * SS) + xx * SS;

    const float* kbase = qkv + (size_t)rowBase * QKVN + 256 + h * HD;
    const float* vbase = qkv + (size_t)rowBase * QKVN + 512 + h * HD;
    const float* qbase = qkv + (size_t)(rowBase + t) * QKVN + h * HD;

    #pragma unroll
    for (int d4 = 0; d4 < 8; d4++) {
        float4 kv = *(const float4*)&kbase[(size_t)t * QKVN + d4 * 4];
        *(float4*)&ks[t][d4 * 4] = kv;
        float4 vv = *(const float4*)&vbase[(size_t)t * QKVN + d4 * 4];
        *(float4*)&vs[t][d4 * 4] = vv;
    }
    msk[t] = g_mask[rowBase + t] ? 1.f : 0.f;

    float q[32];
    #pragma unroll
    for (int d4 = 0; d4 < 8; d4++) {
        float4 qq = *(const float4*)&qbase[d4 * 4];
        q[d4 * 4 + 0] = qq.x; q[d4 * 4 + 1] = qq.y;
        q[d4 * 4 + 2] = qq.z; q[d4 * 4 + 3] = qq.w;
    }
    __syncthreads();

    float o[32];
    #pragma unroll
    for (int d = 0; d < 32; d++) o[d] = 0.f;
    float mx = -3e38f, l = 0.f;

    for (int j = 0; j < 128; j++) {
        float s = 0.f;
        #pragma unroll
        for (int d4 = 0; d4 < 8; d4++) {
            float4 kv = *(const float4*)&ks[j][d4 * 4];
            s += q[d4*4+0]*kv.x + q[d4*4+1]*kv.y + q[d4*4+2]*kv.z + q[d4*4+3]*kv.w;
        }
        s *= 0.17677669529663687f;
        if (msk[j] != 0.f) s = -1e9f;

        if (s <= mx) {
            float w = __expf(s - mx);
            l += w;
            #pragma unroll
            for (int d4 = 0; d4 < 8; d4++) {
                float4 vv = *(const float4*)&vs[j][d4 * 4];
                o[d4*4+0] += w * vv.x; o[d4*4+1] += w * vv.y;
                o[d4*4+2] += w * vv.z; o[d4*4+3] += w * vv.w;
            }
        } else {
            float corr = __expf(mx - s);
            l = l * corr + 1.f;
            #pragma unroll
            for (int d4 = 0; d4 < 8; d4++) {
                float4 vv = *(const float4*)&vs[j][d4 * 4];
                o[d4*4+0] = o[d4*4+0] * corr + vv.x;
                o[d4*4+1] = o[d4*4+1] * corr + vv.y;
                o[d4*4+2] = o[d4*4+2] * corr + vv.z;
                o[d4*4+3] = o[d4*4+3] * corr + vv.w;
            }
            mx = s;
        }
    }

    float rl = 1.f / l;
    size_t ob = (size_t)(rowBase + t) * DD + h * HD;
    #pragma unroll
    for (int d = 0; d < 32; d++) {
        __nv_bfloat16 hh, ll;
        bf16_split(o[d] * rl, hh, ll);
        oh[ob + d] = hh;
        ol[ob + d] = ll;
    }
}

// ===========================================================================
extern "C" void kernel_launch(void* const* d_in, const int* in_sizes, int n_in,
                              void* d_out, int out_size)
{
    const float* pair_act = nullptr;
    const unsigned char* pair_mask = nullptr;
    const float* ln_gamma = nullptr;
    const float* ln_beta  = nullptr;
    const float* Wqkv = nullptr;
    const float* Wout = nullptr;

    for (int i = 0; i < n_in; i++) {
        int sz = in_sizes[i];
        if      (sz == 8388608) pair_act  = (const float*)d_in[i];
        else if (sz == 32768)   pair_mask = (const unsigned char*)d_in[i];
        else if (sz == 196608)  Wqkv      = (const float*)d_in[i];
        else if (sz == 65536)   Wout      = (const float*)d_in[i];
        else if (sz == 256) {
            if (!ln_gamma) ln_gamma = (const float*)d_in[i];
            else           ln_beta  = (const float*)d_in[i];
        }
    }

    float* out = (float*)d_out;

    void *pxh, *pxl, *pqkv, *path, *patl, *pwqh, *pwql, *pwoh, *pwol;
    cudaGetSymbolAddress(&pxh,  g_x_hi);
    cudaGetSymbolAddress(&pxl,  g_x_lo);
    cudaGetSymbolAddress(&pqkv, g_qkv);
    cudaGetSymbolAddress(&path, g_att_hi);
    cudaGetSymbolAddress(&patl, g_att_lo);
    cudaGetSymbolAddress(&pwqh, g_wq_hi);
    cudaGetSymbolAddress(&pwql, g_wq_lo);
    cudaGetSymbolAddress(&pwoh, g_wo_hi);
    cudaGetSymbolAddress(&pwol, g_wo_lo);

    cudaFuncSetAttribute(gemm_bf16_kernel<QKVN, true>,
                         cudaFuncAttributeMaxDynamicSharedMemorySize, GEMM_SMEM);
    cudaFuncSetAttribute(gemm_bf16_kernel<DD, false>,
                         cudaFuncAttributeMaxDynamicSharedMemorySize, GEMM_SMEM);

    detect_mask_kernel<<<1, 256>>>(pair_mask);
    conv_mask_kernel<<<128, 256>>>(pair_mask);

    convw_kernel<<<(QKVN * DD + 255) / 256, 256>>>(
        Wqkv, QKVN * DD, (__nv_bfloat16*)pwqh, (__nv_bfloat16*)pwql);
    convw_kernel<<<(DD * DD + 255) / 256, 256>>>(
        Wout, DD * DD, (__nv_bfloat16*)pwoh, (__nv_bfloat16*)pwol);

    ln_kernel<<<MTOT, 256>>>(pair_act, ln_gamma, ln_beta,
                             (__nv_bfloat16*)pxh, (__nv_bfloat16*)pxl);

    gemm_bf16_kernel<QKVN, true><<<dim3(QKVN / 128, MTOT / 128), 256, GEMM_SMEM>>>(
        (const __nv_bfloat16*)pxh, (const __nv_bfloat16*)pxl,
        (const __nv_bfloat16*)pwqh, (const __nv_bfloat16*)pwql, (float*)pqkv);

    attn_kernel<<<dim3(NH, SS, BB), 128>>>(
        (const float*)pqkv, (__nv_bfloat16*)path, (__nv_bfloat16*)patl);

    gemm_bf16_kernel<DD, false><<<dim3(DD / 128, MTOT / 128), 256, GEMM_SMEM>>>(
        (const __nv_bfloat16*)path, (const __nv_bfloat16*)patl,
        (const __nv_bfloat16*)pwoh, (const __nv_bfloat16*)pwol, out);
}

// round 8
// speedup vs baseline: 2.9579x; 1.5787x over previous
#include <cuda_runtime.h>
#include <cuda_bf16.h>
#include <cstdint>
#include <math.h>

// Problem constants
#define BB 2
#define SS 128
#define DD 256
#define NH 8
#define HD 32
#define MTOT (BB*SS*SS)      // 32768 rows
#define QKVN 768
#define SCALE 0.17677669529663687f

// Scratch (allocation-free rule: __device__ globals)
__device__ __nv_bfloat16 g_x_hi[MTOT * DD];
__device__ __nv_bfloat16 g_x_lo[MTOT * DD];
__device__ float         g_qkv[MTOT * QKVN];
__device__ __nv_bfloat16 g_att_hi[MTOT * DD];
__device__ __nv_bfloat16 g_att_lo[MTOT * DD];
__device__ __nv_bfloat16 g_wq_hi[QKVN * DD];
__device__ __nv_bfloat16 g_wq_lo[QKVN * DD];
__device__ __nv_bfloat16 g_wo_hi[DD * DD];
__device__ __nv_bfloat16 g_wo_lo[DD * DD];
__device__ unsigned char g_mask[32768];
__device__ int g_mask_kind;

// ===========================================================================
// Helpers
// ===========================================================================
__device__ __forceinline__ uint32_t smem_u32(const void* p) {
    uint32_t a;
    asm("{ .reg .u64 t; cvta.to.shared.u64 t, %1; cvt.u32.u64 %0, t; }" : "=r"(a) : "l"(p));
    return a;
}
__device__ __forceinline__ uint32_t swz(uint32_t o) {       // SW128 swizzle
    return o ^ ((o >> 3) & 0x70);
}
__device__ __forceinline__ void bf16_split(float x, __nv_bfloat16& h, __nv_bfloat16& l) {
    h = __float2bfloat16(x);
    l = __float2bfloat16(x - __bfloat162float(h));
}
// pack two floats -> bf16x2 (a in low half = even col, b in high = odd col)
__device__ __forceinline__ uint32_t pack_bf16(float a, float b) {
    __nv_bfloat162 t = __floats2bfloat162_rn(a, b);
    return *(uint32_t*)&t;
}
__device__ __forceinline__ void mma16816(float* c, const uint32_t* a, const uint32_t* b) {
    asm volatile("mma.sync.aligned.m16n8k16.row.col.f32.bf16.bf16.f32 "
        "{%0,%1,%2,%3}, {%4,%5,%6,%7}, {%8,%9}, {%0,%1,%2,%3};"
        : "+f"(c[0]), "+f"(c[1]), "+f"(c[2]), "+f"(c[3])
        : "r"(a[0]), "r"(a[1]), "r"(a[2]), "r"(a[3]), "r"(b[0]), "r"(b[1]));
}
#define LDSM_X4(r, addr) \
    asm volatile("ldmatrix.sync.aligned.m8n8.x4.shared.b16 {%0,%1,%2,%3}, [%4];" \
        : "=r"((r)[0]), "=r"((r)[1]), "=r"((r)[2]), "=r"((r)[3]) : "r"(addr))

// ===========================================================================
// Mask normalization (dtype-sniffing)
// ===========================================================================
__global__ __launch_bounds__(256)
void detect_mask_kernel(const unsigned char* __restrict__ m)
{
    __shared__ int fa, fb;
    if (threadIdx.x == 0) { fa = 0; fb = 0; }
    __syncthreads();
    for (int i = threadIdx.x; i < 32768; i += 256) {
        unsigned char v = m[i];
        if (v) { int r = i & 3; if (r == 1) fa = 1; else if (r == 0) fb = 1; }
    }
    __syncthreads();
    if (threadIdx.x == 0) g_mask_kind = fa ? 0 : (fb ? 1 : 2);
}

__global__ __launch_bounds__(256)
void conv_mask_kernel(const unsigned char* __restrict__ m)
{
    int i = blockIdx.x * 256 + threadIdx.x;
    int kind = g_mask_kind;
    unsigned char v;
    if (kind == 0)      v = m[i] ? 1 : 0;
    else if (kind == 1) v = ((const int*)m)[i] ? 1 : 0;
    else                v = (((const float*)m)[i] != 0.f) ? 1 : 0;
    g_mask[i] = v;
}

// ===========================================================================
// Weight split: fp32 -> bf16 hi/lo
// ===========================================================================
__global__ __launch_bounds__(256)
void convw_kernel(const float* __restrict__ w, int n,
                  __nv_bfloat16* __restrict__ hi, __nv_bfloat16* __restrict__ lo)
{
    int i = blockIdx.x * 256 + threadIdx.x;
    if (i < n) {
        __nv_bfloat16 h, l;
        bf16_split(w[i], h, l);
        hi[i] = h; lo[i] = l;
    }
}

// ===========================================================================
// LayerNorm: one block per row of 256; writes bf16 hi/lo split
// ===========================================================================
__global__ __launch_bounds__(256)
void ln_kernel(const float* __restrict__ in,
               const float* __restrict__ gamma,
               const float* __restrict__ beta,
               __nv_bfloat16* __restrict__ oh,
               __nv_bfloat16* __restrict__ ol)
{
    int row = blockIdx.x;
    int t = threadIdx.x;
    float v = in[(size_t)row * DD + t];
    float s = v, s2 = v * v;
    #pragma unroll
    for (int o = 16; o > 0; o >>= 1) {
        s  += __shfl_xor_sync(0xffffffffu, s,  o);
        s2 += __shfl_xor_sync(0xffffffffu, s2, o);
    }
    __shared__ float ws[8], ws2[8];
    int w = t >> 5, l = t & 31;
    if (l == 0) { ws[w] = s; ws2[w] = s2; }
    __syncthreads();
    float tot = 0.f, tot2 = 0.f;
    #pragma unroll
    for (int i = 0; i < 8; i++) { tot += ws[i]; tot2 += ws2[i]; }
    float mu  = tot * (1.f / 256.f);
    float var = tot2 * (1.f / 256.f) - mu * mu;
    float r   = rsqrtf(var + 1e-5f);
    float y = (v - mu) * r * gamma[t] + beta[t];
    __nv_bfloat16 h, lo2;
    bf16_split(y, h, lo2);
    oh[(size_t)row * DD + t] = h;
    ol[(size_t)row * DD + t] = lo2;
}

// ===========================================================================
// bf16 3-term NT GEMM via mma.sync.
// BM=128, BN=128, BK=64; 256 threads = warps 4(m) x 2(n); warp tile 32x64.
// ===========================================================================
#define OFF_AH 0
#define OFF_AL 16384
#define OFF_BH 32768
#define OFF_BL 49152
#define GEMM_SMEM (65536 + 1024)

template<int N, bool DO_ROT>
__global__ void __launch_bounds__(256)
gemm_bf16_kernel(const __nv_bfloat16* __restrict__ Ah,
                 const __nv_bfloat16* __restrict__ Al,
                 const __nv_bfloat16* __restrict__ Bh,
                 const __nv_bfloat16* __restrict__ Bl,
                 float* __restrict__ C)
{
    extern __shared__ char smem_raw[];
    char* smem = (char*)(((uintptr_t)smem_raw + 1023) & ~(uintptr_t)1023);
    uint32_t sb = smem_u32(smem);

    const int tid = threadIdx.x;
    const int lane = tid & 31;
    const int wid = tid >> 5;
    const int wm = wid & 3;
    const int wn = wid >> 2;
    const int m0 = blockIdx.y * 128;
    const int n0 = blockIdx.x * 128;

    float acc[2][8][4];
    #pragma unroll
    for (int i = 0; i < 2; i++)
        #pragma unroll
        for (int j = 0; j < 8; j++)
            #pragma unroll
            for (int k = 0; k < 4; k++) acc[i][j][k] = 0.f;

    const int aRow = (lane & 15);
    const int aHalf = (lane >> 4) * 16;
    const int bRow = ((lane >> 4) << 3) + (lane & 7);
    const int bHalf = ((lane >> 3) & 1) * 16;

    for (int chunk = 0; chunk < 4; chunk++) {
        int k0 = chunk * 64;
        #pragma unroll
        for (int s = 0; s < 4; s++) {
            int idx = s * 256 + tid;
            int row = idx >> 3;
            int cs  = idx & 7;
            uint32_t so = swz((uint32_t)(row * 128 + cs * 16));
            size_t ga = (size_t)(m0 + row) * 256 + k0 + cs * 8;
            size_t gb = (size_t)(n0 + row) * 256 + k0 + cs * 8;
            *(uint4*)(smem + OFF_AH + so) = *(const uint4*)(Ah + ga);
            *(uint4*)(smem + OFF_AL + so) = *(const uint4*)(Al + ga);
            *(uint4*)(smem + OFF_BH + so) = *(const uint4*)(Bh + gb);
            *(uint4*)(smem + OFF_BL + so) = *(const uint4*)(Bl + gb);
        }
        __syncthreads();

        #pragma unroll
        for (int kk = 0; kk < 4; kk++) {
            int kb = kk * 32;
            uint32_t ah[2][4], al[2][4];
            #pragma unroll
            for (int mt = 0; mt < 2; mt++) {
                uint32_t o = swz((uint32_t)((wm * 32 + mt * 16 + aRow) * 128 + kb + aHalf));
                LDSM_X4(ah[mt], sb + OFF_AH + o);
                LDSM_X4(al[mt], sb + OFF_AL + o);
            }
            #pragma unroll
            for (int p = 0; p < 4; p++) {
                uint32_t bo = swz((uint32_t)((wn * 64 + p * 16 + bRow) * 128 + kb + bHalf));
                uint32_t bh[4], bl[4];
                LDSM_X4(bh, sb + OFF_BH + bo);
                LDSM_X4(bl, sb + OFF_BL + bo);
                #pragma unroll
                for (int t2 = 0; t2 < 2; t2++) {
                    int nt = p * 2 + t2;
                    #pragma unroll
                    for (int mt = 0; mt < 2; mt++) {
                        mma16816(acc[mt][nt], ah[mt], &bh[t2 * 2]);
                        mma16816(acc[mt][nt], ah[mt], &bl[t2 * 2]);
                        mma16816(acc[mt][nt], al[mt], &bh[t2 * 2]);
                    }
                }
            }
        }
        __syncthreads();
    }

    #pragma unroll
    for (int mt = 0; mt < 2; mt++) {
        int row0 = m0 + wm * 32 + mt * 16 + (lane >> 2);
        #pragma unroll
        for (int nt = 0; nt < 8; nt++) {
            int colg = n0 + wn * 64 + nt * 8 + (lane & 3) * 2;
            float d0 = acc[mt][nt][0], d1 = acc[mt][nt][1];
            float d2 = acc[mt][nt][2], d3 = acc[mt][nt][3];
            if (DO_ROT) {
                bool doRot = (colg < 32) || (colg >= 256 && colg < 288);
                if (doRot) {
                    int p = (colg & 31) >> 1;
                    float invf = __expf(-(float)(p & 7) * 1.1512925464970228f);
                    #pragma unroll
                    for (int rr = 0; rr < 2; rr++) {
                        int m = row0 + rr * 8;
                        int xx = (m >> 7) & 127;
                        int yy = m & 127;
                        float pos  = (p < 8) ? (float)xx : (float)yy;
                        float tpos = (2.f * pos - 127.f) * (1.f / 127.f);
                        float sn, cs;
                        __sincosf(tpos * invf, &sn, &cs);
                        if (rr == 0) {
                            float e0 = d0, e1 = d1;
                            d0 = e0 * cs - e1 * sn;
                            d1 = e1 * cs + e0 * sn;
                        } else {
                            float e0 = d2, e1 = d3;
                            d2 = e0 * cs - e1 * sn;
                            d3 = e1 * cs + e0 * sn;
                        }
                    }
                }
            }
            *(float2*)&C[(size_t)row0 * N + colg]       = make_float2(d0, d1);
            *(float2*)&C[(size_t)(row0 + 8) * N + colg] = make_float2(d2, d3);
        }
    }
}

// ===========================================================================
// Tensorized attention. One block per (h, x, b); 4 warps; warp owns 32 q-rows.
// Whole 128x128 score tile in registers -> full softmax (no online pass).
// QK^T and P*V via bf16 3-term mma.sync. P reuses the C-fragment layout as
// the A-fragment of the PV mma (no smem round trip).
//   smem: Q,K as (row, d) 128x32 bf16 rows padded to 80B (conflict-free LDSM)
//         Vt as (d, j) 32x128 bf16 rows padded to 272B
//         bias[128] fp32 additive mask bias
// ===========================================================================
#define AT_QH 0
#define AT_QL 10240
#define AT_KH 20480
#define AT_KL 30720
#define AT_VTH 40960
#define AT_VTL 49664
#define AT_BIAS 58368
#define ATT_SMEM (58880 + 1024)

__global__ void __launch_bounds__(128)
attn_kernel(const float* __restrict__ qkv,
            __nv_bfloat16* __restrict__ oh,
            __nv_bfloat16* __restrict__ ol)
{
    extern __shared__ char smem_raw[];
    char* smem = (char*)(((uintptr_t)smem_raw + 1023) & ~(uintptr_t)1023);
    uint32_t sb = smem_u32(smem);

    const int hd  = blockIdx.x;
    const int xx  = blockIdx.y;
    const int b   = blockIdx.z;
    const int tid = threadIdx.x;
    const int lane = tid & 31;
    const int wm = tid >> 5;           // warp id: rows wm*32..+31
    const int rowBase = b * (SS * SS) + xx * SS;

    // ---- Phase 1: stage Q*scale, K, Vt, bias into smem (thread t = row j) ----
    {
        const float* base = qkv + (size_t)(rowBase + tid) * QKVN + hd * HD;
        float buf[32];

        // Q (scaled)
        #pragma unroll
        for (int g = 0; g < 8; g++) {
            float4 v = *(const float4*)&base[g * 4];
            buf[g*4+0] = v.x * SCALE; buf[g*4+1] = v.y * SCALE;
            buf[g*4+2] = v.z * SCALE; buf[g*4+3] = v.w * SCALE;
        }
        #pragma unroll
        for (int g = 0; g < 4; g++) {
            uint4 h4, l4;
            uint32_t* hp = (uint32_t*)&h4;
            uint32_t* lp = (uint32_t*)&l4;
            #pragma unroll
            for (int q = 0; q < 4; q++) {
                float a = buf[g*8 + q*2], c = buf[g*8 + q*2 + 1];
                __nv_bfloat16 ha, la, hc, lc;
                bf16_split(a, ha, la); bf16_split(c, hc, lc);
                hp[q] = ((uint32_t)*(uint16_t*)&hc << 16) | *(uint16_t*)&ha;
                lp[q] = ((uint32_t)*(uint16_t*)&lc << 16) | *(uint16_t*)&la;
            }
            *(uint4*)(smem + AT_QH + tid * 80 + g * 16) = h4;
            *(uint4*)(smem + AT_QL + tid * 80 + g * 16) = l4;
        }

        // K
        #pragma unroll
        for (int g = 0; g < 8; g++) {
            float4 v = *(const float4*)&base[256 + g * 4];
            buf[g*4+0] = v.x; buf[g*4+1] = v.y; buf[g*4+2] = v.z; buf[g*4+3] = v.w;
        }
        #pragma unroll
        for (int g = 0; g < 4; g++) {
            uint4 h4, l4;
            uint32_t* hp = (uint32_t*)&h4;
            uint32_t* lp = (uint32_t*)&l4;
            #pragma unroll
            for (int q = 0; q < 4; q++) {
                float a = buf[g*8 + q*2], c = buf[g*8 + q*2 + 1];
                __nv_bfloat16 ha, la, hc, lc;
                bf16_split(a, ha, la); bf16_split(c, hc, lc);
                hp[q] = ((uint32_t)*(uint16_t*)&hc << 16) | *(uint16_t*)&ha;
                lp[q] = ((uint32_t)*(uint16_t*)&lc << 16) | *(uint16_t*)&la;
            }
            *(uint4*)(smem + AT_KH + tid * 80 + g * 16) = h4;
            *(uint4*)(smem + AT_KL + tid * 80 + g * 16) = l4;
        }

        // V -> Vt (transposed scalar stores)
        #pragma unroll
        for (int g = 0; g < 8; g++) {
            float4 v = *(const float4*)&base[512 + g * 4];
            buf[g*4+0] = v.x; buf[g*4+1] = v.y; buf[g*4+2] = v.z; buf[g*4+3] = v.w;
        }
        #pragma unroll
        for (int d = 0; d < 32; d++) {
            __nv_bfloat16 h, l;
            bf16_split(buf[d], h, l);
            *(__nv_bfloat16*)(smem + AT_VTH + d * 272 + tid * 2) = h;
            *(__nv_bfloat16*)(smem + AT_VTL + d * 272 + tid * 2) = l;
        }

        // bias
        *(float*)(smem + AT_BIAS + tid * 4) = g_mask[rowBase + tid] ? -1e9f : 0.f;
    }
    __syncthreads();

    const int aRow = (lane & 15);
    const int aHalf = (lane >> 4) * 16;
    const int bRow = ((lane >> 4) << 3) + (lane & 7);
    const int bHalf = ((lane >> 3) & 1) * 16;

    // ---- Phase 2: S = Q K^T (3-term bf16) ----
    float acc[2][16][4];
    #pragma unroll
    for (int i = 0; i < 2; i++)
        #pragma unroll
        for (int j = 0; j < 16; j++)
            #pragma unroll
            for (int k = 0; k < 4; k++) acc[i][j][k] = 0.f;

    #pragma unroll
    for (int kk = 0; kk < 2; kk++) {
        uint32_t ah[2][4], al[2][4];
        #pragma unroll
        for (int mt = 0; mt < 2; mt++) {
            uint32_t o = (uint32_t)((wm * 32 + mt * 16 + aRow) * 80 + kk * 32 + aHalf);
            LDSM_X4(ah[mt], sb + AT_QH + o);
            LDSM_X4(al[mt], sb + AT_QL + o);
        }
        #pragma unroll
        for (int p = 0; p < 8; p++) {
            uint32_t bo = (uint32_t)((p * 16 + bRow) * 80 + kk * 32 + bHalf);
            uint32_t bh[4], bl[4];
            LDSM_X4(bh, sb + AT_KH + bo);
            LDSM_X4(bl, sb + AT_KL + bo);
            #pragma unroll
            for (int t2 = 0; t2 < 2; t2++) {
                int nt = p * 2 + t2;
                #pragma unroll
                for (int mt = 0; mt < 2; mt++) {
                    mma16816(acc[mt][nt], ah[mt], &bh[t2 * 2]);
                    mma16816(acc[mt][nt], ah[mt], &bl[t2 * 2]);
                    mma16816(acc[mt][nt], al[mt], &bh[t2 * 2]);
                }
            }
        }
    }

    // ---- Phase 3: full softmax in registers + P hi/lo fragments ----
    uint32_t Ph[2][8][4], Pl[2][8][4];
    float rsum[2][2];

    #pragma unroll
    for (int mt = 0; mt < 2; mt++) {
        float mx0 = -3e38f, mx1 = -3e38f;
        #pragma unroll
        for (int nt = 0; nt < 16; nt++) {
            float2 bb = *(float2*)(smem + AT_BIAS + (nt * 8 + 2 * (lane & 3)) * 4);
            acc[mt][nt][0] += bb.x; acc[mt][nt][1] += bb.y;
            acc[mt][nt][2] += bb.x; acc[mt][nt][3] += bb.y;
            mx0 = fmaxf(mx0, fmaxf(acc[mt][nt][0], acc[mt][nt][1]));
            mx1 = fmaxf(mx1, fmaxf(acc[mt][nt][2], acc[mt][nt][3]));
        }
        mx0 = fmaxf(mx0, __shfl_xor_sync(0xffffffffu, mx0, 1));
        mx0 = fmaxf(mx0, __shfl_xor_sync(0xffffffffu, mx0, 2));
        mx1 = fmaxf(mx1, __shfl_xor_sync(0xffffffffu, mx1, 1));
        mx1 = fmaxf(mx1, __shfl_xor_sync(0xffffffffu, mx1, 2));

        float s0 = 0.f, s1 = 0.f;
        #pragma unroll
        for (int nt = 0; nt < 16; nt++) {
            float e0 = __expf(acc[mt][nt][0] - mx0);
            float e1 = __expf(acc[mt][nt][1] - mx0);
            float e2 = __expf(acc[mt][nt][2] - mx1);
            float e3 = __expf(acc[mt][nt][3] - mx1);
            acc[mt][nt][0] = e0; acc[mt][nt][1] = e1;
            acc[mt][nt][2] = e2; acc[mt][nt][3] = e3;
            s0 += e0 + e1; s1 += e2 + e3;
        }
        s0 += __shfl_xor_sync(0xffffffffu, s0, 1);
        s0 += __shfl_xor_sync(0xffffffffu, s0, 2);
        s1 += __shfl_xor_sync(0xffffffffu, s1, 1);
        s1 += __shfl_xor_sync(0xffffffffu, s1, 2);
        rsum[mt][0] = s0; rsum[mt][1] = s1;

        // pack P into A-fragment layout (C-frag == A-frag mapping)
        #pragma unroll
        for (int kt = 0; kt < 8; kt++) {
            #pragma unroll
            for (int half = 0; half < 2; half++) {       // half: n8 tile 2kt / 2kt+1
                const float* c = acc[mt][2 * kt + half];
                __nv_bfloat16 h0, l0, h1, l1, h2, l2, h3, l3;
                bf16_split(c[0], h0, l0); bf16_split(c[1], h1, l1);
                bf16_split(c[2], h2, l2); bf16_split(c[3], h3, l3);
                Ph[mt][kt][half * 2 + 0] = ((uint32_t)*(uint16_t*)&h1 << 16) | *(uint16_t*)&h0;
                Ph[mt][kt][half * 2 + 1] = ((uint32_t)*(uint16_t*)&h3 << 16) | *(uint16_t*)&h2;
                Pl[mt][kt][half * 2 + 0] = ((uint32_t)*(uint16_t*)&l1 << 16) | *(uint16_t*)&l0;
                Pl[mt][kt][half * 2 + 1] = ((uint32_t)*(uint16_t*)&l3 << 16) | *(uint16_t*)&l2;
            }
        }
    }

    // ---- Phase 4: O = P V (3-term) ----
    float pacc[2][4][4];
    #pragma unroll
    for (int i = 0; i < 2; i++)
        #pragma unroll
        for (int j = 0; j < 4; j++)
            #pragma unroll
            for (int k = 0; k < 4; k++) pacc[i][j][k] = 0.f;

    #pragma unroll
    for (int kt = 0; kt < 8; kt++) {
        #pragma unroll
        for (int p2 = 0; p2 < 2; p2++) {
            uint32_t vo = (uint32_t)((p2 * 16 + bRow) * 272 + kt * 32 + bHalf);
            uint32_t vh[4], vl[4];
            LDSM_X4(vh, sb + AT_VTH + vo);
            LDSM_X4(vl, sb + AT_VTL + vo);
            #pragma unroll
            for (int t2 = 0; t2 < 2; t2++) {
                int nt = p2 * 2 + t2;
                #pragma unroll
                for (int mt = 0; mt < 2; mt++) {
                    mma16816(pacc[mt][nt], Ph[mt][kt], &vh[t2 * 2]);
                    mma16816(pacc[mt][nt], Ph[mt][kt], &vl[t2 * 2]);
                    mma16816(pacc[mt][nt], Pl[mt][kt], &vh[t2 * 2]);
                }
            }
        }
    }

    // ---- Phase 5: epilogue (divide by row sum, store bf16 hi/lo) ----
    #pragma unroll
    for (int mt = 0; mt < 2; mt++) {
        float r0 = 1.f / rsum[mt][0];
        float r1 = 1.f / rsum[mt][1];
        int row0 = rowBase + wm * 32 + mt * 16 + (lane >> 2);
        #pragma unroll
        for (int nt = 0; nt < 4; nt++) {
            int col = hd * HD + nt * 8 + 2 * (lane & 3);
            float v0 = pacc[mt][nt][0] * r0, v1 = pacc[mt][nt][1] * r0;
            float v2 = pacc[mt][nt][2] * r1, v3 = pacc[mt][nt][3] * r1;
            __nv_bfloat16 h0, l0, h1, l1, h2, l2, h3, l3;
            bf16_split(v0, h0, l0); bf16_split(v1, h1, l1);
            bf16_split(v2, h2, l2); bf16_split(v3, h3, l3);
            size_t base0 = (size_t)row0 * DD + col;
            size_t base1 = (size_t)(row0 + 8) * DD + col;
            *(uint32_t*)((char*)oh + base0 * 2) = ((uint32_t)*(uint16_t*)&h1 << 16) | *(uint16_t*)&h0;
            *(uint32_t*)((char*)ol + base0 * 2) = ((uint32_t)*(uint16_t*)&l1 << 16) | *(uint16_t*)&l0;
            *(uint32_t*)((char*)oh + base1 * 2) = ((uint32_t)*(uint16_t*)&h3 << 16) | *(uint16_t*)&h2;
            *(uint32_t*)((char*)ol + base1 * 2) = ((uint32_t)*(uint16_t*)&l3 << 16) | *(uint16_t*)&l2;
        }
    }
}

// ===========================================================================
extern "C" void kernel_launch(void* const* d_in, const int* in_sizes, int n_in,
                              void* d_out, int out_size)
{
    const float* pair_act = nullptr;
    const unsigned char* pair_mask = nullptr;
    const float* ln_gamma = nullptr;
    const float* ln_beta  = nullptr;
    const float* Wqkv = nullptr;
    const float* Wout = nullptr;

    for (int i = 0; i < n_in; i++) {
        int sz = in_sizes[i];
        if      (sz == 8388608) pair_act  = (const float*)d_in[i];
        else if (sz == 32768)   pair_mask = (const unsigned char*)d_in[i];
        else if (sz == 196608)  Wqkv      = (const float*)d_in[i];
        else if (sz == 65536)   Wout      = (const float*)d_in[i];
        else if (sz == 256) {
            if (!ln_gamma) ln_gamma = (const float*)d_in[i];
            else           ln_beta  = (const float*)d_in[i];
        }
    }

    float* out = (float*)d_out;

    void *pxh, *pxl, *pqkv, *path, *patl, *pwqh, *pwql, *pwoh, *pwol;
    cudaGetSymbolAddress(&pxh,  g_x_hi);
    cudaGetSymbolAddress(&pxl,  g_x_lo);
    cudaGetSymbolAddress(&pqkv, g_qkv);
    cudaGetSymbolAddress(&path, g_att_hi);
    cudaGetSymbolAddress(&patl, g_att_lo);
    cudaGetSymbolAddress(&pwqh, g_wq_hi);
    cudaGetSymbolAddress(&pwql, g_wq_lo);
    cudaGetSymbolAddress(&pwoh, g_wo_hi);
    cudaGetSymbolAddress(&pwol, g_wo_lo);

    cudaFuncSetAttribute(gemm_bf16_kernel<QKVN, true>,
                         cudaFuncAttributeMaxDynamicSharedMemorySize, GEMM_SMEM);
    cudaFuncSetAttribute(gemm_bf16_kernel<DD, false>,
                         cudaFuncAttributeMaxDynamicSharedMemorySize, GEMM_SMEM);
    cudaFuncSetAttribute(attn_kernel,
                         cudaFuncAttributeMaxDynamicSharedMemorySize, ATT_SMEM);

    detect_mask_kernel<<<1, 256>>>(pair_mask);
    conv_mask_kernel<<<128, 256>>>(pair_mask);

    convw_kernel<<<(QKVN * DD + 255) / 256, 256>>>(
        Wqkv, QKVN * DD, (__nv_bfloat16*)pwqh, (__nv_bfloat16*)pwql);
    convw_kernel<<<(DD * DD + 255) / 256, 256>>>(
        Wout, DD * DD, (__nv_bfloat16*)pwoh, (__nv_bfloat16*)pwol);

    ln_kernel<<<MTOT, 256>>>(pair_act, ln_gamma, ln_beta,
                             (__nv_bfloat16*)pxh, (__nv_bfloat16*)pxl);

    gemm_bf16_kernel<QKVN, true><<<dim3(QKVN / 128, MTOT / 128), 256, GEMM_SMEM>>>(
        (const __nv_bfloat16*)pxh, (const __nv_bfloat16*)pxl,
        (const __nv_bfloat16*)pwqh, (const __nv_bfloat16*)pwql, (float*)pqkv);

    attn_kernel<<<dim3(NH, SS, BB), 128, ATT_SMEM>>>(
        (const float*)pqkv, (__nv_bfloat16*)path, (__nv_bfloat16*)patl);

    gemm_bf16_kernel<DD, false><<<dim3(DD / 128, MTOT / 128), 256, GEMM_SMEM>>>(
        (const __nv_bfloat16*)path, (const __nv_bfloat16*)patl,
        (const __nv_bfloat16*)pwoh, (const __nv_bfloat16*)pwol, out);
}

// round 9
// speedup vs baseline: 3.1477x; 1.0642x over previous
#include <cuda_runtime.h>
#include <cuda_bf16.h>
#include <cstdint>
#include <math.h>

// Problem constants
#define BB 2
#define SS 128
#define DD 256
#define NH 8
#define HD 32
#define MTOT (BB*SS*SS)      // 32768 rows
#define QKVN 768
#define SCALE 0.17677669529663687f

// Scratch (allocation-free rule: __device__ globals)
__device__ __nv_bfloat16 g_x_hi[MTOT * DD];
__device__ __nv_bfloat16 g_x_lo[MTOT * DD];
__device__ __nv_bfloat16 g_qkv_hi[MTOT * QKVN];
__device__ __nv_bfloat16 g_qkv_lo[MTOT * QKVN];
__device__ __nv_bfloat16 g_att_hi[MTOT * DD];
__device__ __nv_bfloat16 g_att_lo[MTOT * DD];
__device__ __nv_bfloat16 g_wq_hi[QKVN * DD];
__device__ __nv_bfloat16 g_wq_lo[QKVN * DD];
__device__ __nv_bfloat16 g_wo_hi[DD * DD];
__device__ __nv_bfloat16 g_wo_lo[DD * DD];
__device__ unsigned char g_mask[32768];
__device__ int g_mask_kind;

// ===========================================================================
// Helpers
// ===========================================================================
__device__ __forceinline__ uint32_t smem_u32(const void* p) {
    uint32_t a;
    asm("{ .reg .u64 t; cvta.to.shared.u64 t, %1; cvt.u32.u64 %0, t; }" : "=r"(a) : "l"(p));
    return a;
}
__device__ __forceinline__ uint32_t swz(uint32_t o) {       // SW128 swizzle
    return o ^ ((o >> 3) & 0x70);
}
__device__ __forceinline__ void bf16_split(float x, __nv_bfloat16& h, __nv_bfloat16& l) {
    h = __float2bfloat16(x);
    l = __float2bfloat16(x - __bfloat162float(h));
}
__device__ __forceinline__ void mma16816(float* c, const uint32_t* a, const uint32_t* b) {
    asm volatile("mma.sync.aligned.m16n8k16.row.col.f32.bf16.bf16.f32 "
        "{%0,%1,%2,%3}, {%4,%5,%6,%7}, {%8,%9}, {%0,%1,%2,%3};"
        : "+f"(c[0]), "+f"(c[1]), "+f"(c[2]), "+f"(c[3])
        : "r"(a[0]), "r"(a[1]), "r"(a[2]), "r"(a[3]), "r"(b[0]), "r"(b[1]));
}
#define LDSM_X4(r, addr) \
    asm volatile("ldmatrix.sync.aligned.m8n8.x4.shared.b16 {%0,%1,%2,%3}, [%4];" \
        : "=r"((r)[0]), "=r"((r)[1]), "=r"((r)[2]), "=r"((r)[3]) : "r"(addr))
#define LDSM_X4_T(r, addr) \
    asm volatile("ldmatrix.sync.aligned.m8n8.x4.trans.shared.b16 {%0,%1,%2,%3}, [%4];" \
        : "=r"((r)[0]), "=r"((r)[1]), "=r"((r)[2]), "=r"((r)[3]) : "r"(addr))
__device__ __forceinline__ void cpa16(uint32_t s, const void* g) {
    asm volatile("cp.async.cg.shared.global [%0], [%1], 16;" :: "r"(s), "l"(g));
}
#define CPA_COMMIT() asm volatile("cp.async.commit_group;" ::: "memory")
#define CPA_WAIT0() asm volatile("cp.async.wait_group 0;" ::: "memory")
#define CPA_WAIT1() asm volatile("cp.async.wait_group 1;" ::: "memory")

// ===========================================================================
// Mask normalization (dtype-sniffing)
// ===========================================================================
__global__ __launch_bounds__(256)
void detect_mask_kernel(const unsigned char* __restrict__ m)
{
    __shared__ int fa, fb;
    if (threadIdx.x == 0) { fa = 0; fb = 0; }
    __syncthreads();
    for (int i = threadIdx.x; i < 32768; i += 256) {
        unsigned char v = m[i];
        if (v) { int r = i & 3; if (r == 1) fa = 1; else if (r == 0) fb = 1; }
    }
    __syncthreads();
    if (threadIdx.x == 0) g_mask_kind = fa ? 0 : (fb ? 1 : 2);
}

__global__ __launch_bounds__(256)
void conv_mask_kernel(const unsigned char* __restrict__ m)
{
    int i = blockIdx.x * 256 + threadIdx.x;
    int kind = g_mask_kind;
    unsigned char v;
    if (kind == 0)      v = m[i] ? 1 : 0;
    else if (kind == 1) v = ((const int*)m)[i] ? 1 : 0;
    else                v = (((const float*)m)[i] != 0.f) ? 1 : 0;
    g_mask[i] = v;
}

// ===========================================================================
// Weight split: fp32 -> bf16 hi/lo
// ===========================================================================
__global__ __launch_bounds__(256)
void convw_kernel(const float* __restrict__ w, int n,
                  __nv_bfloat16* __restrict__ hi, __nv_bfloat16* __restrict__ lo)
{
    int i = blockIdx.x * 256 + threadIdx.x;
    if (i < n) {
        __nv_bfloat16 h, l;
        bf16_split(w[i], h, l);
        hi[i] = h; lo[i] = l;
    }
}

// ===========================================================================
// LayerNorm: one block per row of 256; writes bf16 hi/lo split
// ===========================================================================
__global__ __launch_bounds__(256)
void ln_kernel(const float* __restrict__ in,
               const float* __restrict__ gamma,
               const float* __restrict__ beta,
               __nv_bfloat16* __restrict__ oh,
               __nv_bfloat16* __restrict__ ol)
{
    int row = blockIdx.x;
    int t = threadIdx.x;
    float v = in[(size_t)row * DD + t];
    float s = v, s2 = v * v;
    #pragma unroll
    for (int o = 16; o > 0; o >>= 1) {
        s  += __shfl_xor_sync(0xffffffffu, s,  o);
        s2 += __shfl_xor_sync(0xffffffffu, s2, o);
    }
    __shared__ float ws[8], ws2[8];
    int w = t >> 5, l = t & 31;
    if (l == 0) { ws[w] = s; ws2[w] = s2; }
    __syncthreads();
    float tot = 0.f, tot2 = 0.f;
    #pragma unroll
    for (int i = 0; i < 8; i++) { tot += ws[i]; tot2 += ws2[i]; }
    float mu  = tot * (1.f / 256.f);
    float var = tot2 * (1.f / 256.f) - mu * mu;
    float r   = rsqrtf(var + 1e-5f);
    float y = (v - mu) * r * gamma[t] + beta[t];
    __nv_bfloat16 h, lo2;
    bf16_split(y, h, lo2);
    oh[(size_t)row * DD + t] = h;
    ol[(size_t)row * DD + t] = lo2;
}

// ===========================================================================
// bf16 3-term NT GEMM via mma.sync, cp.async double-buffered.
// BM=128, BN=128, BK=64; 256 threads = warps 4(m) x 2(n); warp tile 32x64.
// MODE 0: fp32 output C.
// MODE 1 (QKV): fused rotary (q/k head0) + q-scale, bf16 hi/lo split output.
// ===========================================================================
#define OFF_AH 0
#define OFF_AL 16384
#define OFF_BH 32768
#define OFF_BL 49152
#define STAGE_SZ 65536
#define GEMM_SMEM (2*STAGE_SZ + 1024)

template<int N, int MODE>
__global__ void __launch_bounds__(256)
gemm_bf16_kernel(const __nv_bfloat16* __restrict__ Ah,
                 const __nv_bfloat16* __restrict__ Al,
                 const __nv_bfloat16* __restrict__ Bh,
                 const __nv_bfloat16* __restrict__ Bl,
                 float* __restrict__ C,
                 __nv_bfloat16* __restrict__ Ch,
                 __nv_bfloat16* __restrict__ Cl)
{
    extern __shared__ char smem_raw[];
    char* smem = (char*)(((uintptr_t)smem_raw + 1023) & ~(uintptr_t)1023);
    uint32_t sb = smem_u32(smem);

    const int tid = threadIdx.x;
    const int lane = tid & 31;
    const int wid = tid >> 5;
    const int wm = wid & 3;
    const int wn = wid >> 2;
    const int m0 = blockIdx.y * 128;
    const int n0 = blockIdx.x * 128;

    float acc[2][8][4];
    #pragma unroll
    for (int i = 0; i < 2; i++)
        #pragma unroll
        for (int j = 0; j < 8; j++)
            #pragma unroll
            for (int k = 0; k < 4; k++) acc[i][j][k] = 0.f;

    const int aRow = (lane & 15);
    const int aHalf = (lane >> 4) * 16;
    const int bRow = ((lane >> 4) << 3) + (lane & 7);
    const int bHalf = ((lane >> 3) & 1) * 16;

    const int ldRow = tid >> 3;          // 0..31 per s-step block of 32 rows
    const int ldCs  = tid & 7;

    // issue cp.async loads for one 64-wide k chunk into stage buffer
    auto load_chunk = [&](int chunk, int buf) {
        int k0 = chunk * 64;
        uint32_t stage = sb + (uint32_t)buf * STAGE_SZ;
        #pragma unroll
        for (int s = 0; s < 4; s++) {
            int row = s * 32 + ldRow;
            uint32_t so = swz((uint32_t)(row * 128 + ldCs * 16));
            size_t ga = (size_t)(m0 + row) * 256 + k0 + ldCs * 8;
            size_t gb = (size_t)(n0 + row) * 256 + k0 + ldCs * 8;
            cpa16(stage + OFF_AH + so, Ah + ga);
            cpa16(stage + OFF_AL + so, Al + ga);
            cpa16(stage + OFF_BH + so, Bh + gb);
            cpa16(stage + OFF_BL + so, Bl + gb);
        }
        CPA_COMMIT();
    };

    load_chunk(0, 0);

    for (int chunk = 0; chunk < 4; chunk++) {
        if (chunk < 3) {
            load_chunk(chunk + 1, (chunk + 1) & 1);
            CPA_WAIT1();
        } else {
            CPA_WAIT0();
        }
        __syncthreads();

        uint32_t stage = sb + (uint32_t)(chunk & 1) * STAGE_SZ;
        #pragma unroll
        for (int kk = 0; kk < 4; kk++) {
            int kb = kk * 32;
            uint32_t ah[2][4], al[2][4];
            #pragma unroll
            for (int mt = 0; mt < 2; mt++) {
                uint32_t o = swz((uint32_t)((wm * 32 + mt * 16 + aRow) * 128 + kb + aHalf));
                LDSM_X4(ah[mt], stage + OFF_AH + o);
                LDSM_X4(al[mt], stage + OFF_AL + o);
            }
            #pragma unroll
            for (int p = 0; p < 4; p++) {
                uint32_t bo = swz((uint32_t)((wn * 64 + p * 16 + bRow) * 128 + kb + bHalf));
                uint32_t bh[4], bl[4];
                LDSM_X4(bh, stage + OFF_BH + bo);
                LDSM_X4(bl, stage + OFF_BL + bo);
                #pragma unroll
                for (int t2 = 0; t2 < 2; t2++) {
                    int nt = p * 2 + t2;
                    #pragma unroll
                    for (int mt = 0; mt < 2; mt++) {
                        mma16816(acc[mt][nt], ah[mt], &bh[t2 * 2]);
                        mma16816(acc[mt][nt], ah[mt], &bl[t2 * 2]);
                        mma16816(acc[mt][nt], al[mt], &bh[t2 * 2]);
                    }
                }
            }
        }
        __syncthreads();
    }

    #pragma unroll
    for (int mt = 0; mt < 2; mt++) {
        int row0 = m0 + wm * 32 + mt * 16 + (lane >> 2);
        #pragma unroll
        for (int nt = 0; nt < 8; nt++) {
            int colg = n0 + wn * 64 + nt * 8 + (lane & 3) * 2;
            float d0 = acc[mt][nt][0], d1 = acc[mt][nt][1];
            float d2 = acc[mt][nt][2], d3 = acc[mt][nt][3];
            if (MODE == 1) {
                // rotary on q head0 (cols 0..31) and k head0 (cols 256..287)
                if (colg < 32 || (colg >= 256 && colg < 288)) {
                    int p = (colg & 31) >> 1;
                    float invf = __expf(-(float)(p & 7) * 1.1512925464970228f);
                    #pragma unroll
                    for (int rr = 0; rr < 2; rr++) {
                        int m = row0 + rr * 8;
                        int xx = (m >> 7) & 127;
                        int yy = m & 127;
                        float pos  = (p < 8) ? (float)xx : (float)yy;
                        float tpos = (2.f * pos - 127.f) * (1.f / 127.f);
                        float sn, cs;
                        __sincosf(tpos * invf, &sn, &cs);
                        if (rr == 0) {
                            float e0 = d0, e1 = d1;
                            d0 = e0 * cs - e1 * sn;
                            d1 = e1 * cs + e0 * sn;
                        } else {
                            float e0 = d2, e1 = d3;
                            d2 = e0 * cs - e1 * sn;
                            d3 = e1 * cs + e0 * sn;
                        }
                    }
                }
                // scale all q columns (scale commutes with rotation)
                if (colg < 256) {
                    d0 *= SCALE; d1 *= SCALE; d2 *= SCALE; d3 *= SCALE;
                }
                __nv_bfloat16 h0, l0, h1, l1, h2, l2, h3, l3;
                bf16_split(d0, h0, l0); bf16_split(d1, h1, l1);
                bf16_split(d2, h2, l2); bf16_split(d3, h3, l3);
                size_t b0 = (size_t)row0 * N + colg;
                size_t b1 = (size_t)(row0 + 8) * N + colg;
                *(uint32_t*)((char*)Ch + b0 * 2) = ((uint32_t)*(uint16_t*)&h1 << 16) | *(uint16_t*)&h0;
                *(uint32_t*)((char*)Cl + b0 * 2) = ((uint32_t)*(uint16_t*)&l1 << 16) | *(uint16_t*)&l0;
                *(uint32_t*)((char*)Ch + b1 * 2) = ((uint32_t)*(uint16_t*)&h3 << 16) | *(uint16_t*)&h2;
                *(uint32_t*)((char*)Cl + b1 * 2) = ((uint32_t)*(uint16_t*)&l3 << 16) | *(uint16_t*)&l2;
            } else {
                *(float2*)&C[(size_t)row0 * N + colg]       = make_float2(d0, d1);
                *(float2*)&C[(size_t)(row0 + 8) * N + colg] = make_float2(d2, d3);
            }
        }
    }
}

// ===========================================================================
// Tensorized attention. One block per (h, x, b); 4 warps; warp owns 32 q-rows.
// qkv arrives pre-split bf16 hi/lo with q pre-scaled and rotary applied.
// V kept in row layout; PV uses ldmatrix.trans (no scalar transpose).
//   smem rows: 32 bf16 = 64B padded to 80B (conflict-free LDSM).
// ===========================================================================
#define AT_QH 0
#define AT_QL 10240
#define AT_KH 20480
#define AT_KL 30720
#define AT_VH 40960
#define AT_VL 51200
#define AT_BIAS 61440
#define ATT_SMEM (61952 + 1024)

__global__ void __launch_bounds__(128)
attn_kernel(const __nv_bfloat16* __restrict__ qh,
            const __nv_bfloat16* __restrict__ ql,
            __nv_bfloat16* __restrict__ oh,
            __nv_bfloat16* __restrict__ ol)
{
    extern __shared__ char smem_raw[];
    char* smem = (char*)(((uintptr_t)smem_raw + 1023) & ~(uintptr_t)1023);
    uint32_t sb = smem_u32(smem);

    const int hd  = blockIdx.x;
    const int xx  = blockIdx.y;
    const int b   = blockIdx.z;
    const int tid = threadIdx.x;
    const int lane = tid & 31;
    const int wm = tid >> 5;
    const int rowBase = b * (SS * SS) + xx * SS;

    // ---- Phase 1: pure vectorized staging (thread t = row t) ----
    {
        const char* ph = (const char*)(qh + (size_t)(rowBase + tid) * QKVN + hd * HD);
        const char* pl = (const char*)(ql + (size_t)(rowBase + tid) * QKVN + hd * HD);
        #pragma unroll
        for (int g = 0; g < 4; g++) {
            *(uint4*)(smem + AT_QH + tid * 80 + g * 16) = *(const uint4*)(ph + g * 16);
            *(uint4*)(smem + AT_QL + tid * 80 + g * 16) = *(const uint4*)(pl + g * 16);
            *(uint4*)(smem + AT_KH + tid * 80 + g * 16) = *(const uint4*)(ph + 512 + g * 16);
            *(uint4*)(smem + AT_KL + tid * 80 + g * 16) = *(const uint4*)(pl + 512 + g * 16);
            *(uint4*)(smem + AT_VH + tid * 80 + g * 16) = *(const uint4*)(ph + 1024 + g * 16);
            *(uint4*)(smem + AT_VL + tid * 80 + g * 16) = *(const uint4*)(pl + 1024 + g * 16);
        }
        *(float*)(smem + AT_BIAS + tid * 4) = g_mask[rowBase + tid] ? -1e9f : 0.f;
    }
    __syncthreads();

    const int aRow = (lane & 15);
    const int aHalf = (lane >> 4) * 16;
    const int bRow = ((lane >> 4) << 3) + (lane & 7);
    const int bHalf = ((lane >> 3) & 1) * 16;

    // ---- Phase 2: S = Q K^T (3-term bf16) ----
    float acc[2][16][4];
    #pragma unroll
    for (int i = 0; i < 2; i++)
        #pragma unroll
        for (int j = 0; j < 16; j++)
            #pragma unroll
            for (int k = 0; k < 4; k++) acc[i][j][k] = 0.f;

    #pragma unroll
    for (int kk = 0; kk < 2; kk++) {
        uint32_t ah[2][4], al[2][4];
        #pragma unroll
        for (int mt = 0; mt < 2; mt++) {
            uint32_t o = (uint32_t)((wm * 32 + mt * 16 + aRow) * 80 + kk * 32 + aHalf);
            LDSM_X4(ah[mt], sb + AT_QH + o);
            LDSM_X4(al[mt], sb + AT_QL + o);
        }
        #pragma unroll
        for (int p = 0; p < 8; p++) {
            uint32_t bo = (uint32_t)((p * 16 + bRow) * 80 + kk * 32 + bHalf);
            uint32_t bh[4], bl[4];
            LDSM_X4(bh, sb + AT_KH + bo);
            LDSM_X4(bl, sb + AT_KL + bo);
            #pragma unroll
            for (int t2 = 0; t2 < 2; t2++) {
                int nt = p * 2 + t2;
                #pragma unroll
                for (int mt = 0; mt < 2; mt++) {
                    mma16816(acc[mt][nt], ah[mt], &bh[t2 * 2]);
                    mma16816(acc[mt][nt], ah[mt], &bl[t2 * 2]);
                    mma16816(acc[mt][nt], al[mt], &bh[t2 * 2]);
                }
            }
        }
    }

    // ---- Phase 3: full softmax in registers + P hi/lo fragments ----
    uint32_t Ph[2][8][4], Pl[2][8][4];
    float rsum[2][2];

    #pragma unroll
    for (int mt = 0; mt < 2; mt++) {
        float mx0 = -3e38f, mx1 = -3e38f;
        #pragma unroll
        for (int nt = 0; nt < 16; nt++) {
            float2 bb = *(float2*)(smem + AT_BIAS + (nt * 8 + 2 * (lane & 3)) * 4);
            acc[mt][nt][0] += bb.x; acc[mt][nt][1] += bb.y;
            acc[mt][nt][2] += bb.x; acc[mt][nt][3] += bb.y;
            mx0 = fmaxf(mx0, fmaxf(acc[mt][nt][0], acc[mt][nt][1]));
            mx1 = fmaxf(mx1, fmaxf(acc[mt][nt][2], acc[mt][nt][3]));
        }
        mx0 = fmaxf(mx0, __shfl_xor_sync(0xffffffffu, mx0, 1));
        mx0 = fmaxf(mx0, __shfl_xor_sync(0xffffffffu, mx0, 2));
        mx1 = fmaxf(mx1, __shfl_xor_sync(0xffffffffu, mx1, 1));
        mx1 = fmaxf(mx1, __shfl_xor_sync(0xffffffffu, mx1, 2));

        float s0 = 0.f, s1 = 0.f;
        #pragma unroll
        for (int nt = 0; nt < 16; nt++) {
            float e0 = __expf(acc[mt][nt][0] - mx0);
            float e1 = __expf(acc[mt][nt][1] - mx0);
            float e2 = __expf(acc[mt][nt][2] - mx1);
            float e3 = __expf(acc[mt][nt][3] - mx1);
            acc[mt][nt][0] = e0; acc[mt][nt][1] = e1;
            acc[mt][nt][2] = e2; acc[mt][nt][3] = e3;
            s0 += e0 + e1; s1 += e2 + e3;
        }
        s0 += __shfl_xor_sync(0xffffffffu, s0, 1);
        s0 += __shfl_xor_sync(0xffffffffu, s0, 2);
        s1 += __shfl_xor_sync(0xffffffffu, s1, 1);
        s1 += __shfl_xor_sync(0xffffffffu, s1, 2);
        rsum[mt][0] = s0; rsum[mt][1] = s1;

        #pragma unroll
        for (int kt = 0; kt < 8; kt++) {
            #pragma unroll
            for (int half = 0; half < 2; half++) {
                const float* c = acc[mt][2 * kt + half];
                __nv_bfloat16 h0, l0, h1, l1, h2, l2, h3, l3;
                bf16_split(c[0], h0, l0); bf16_split(c[1], h1, l1);
                bf16_split(c[2], h2, l2); bf16_split(c[3], h3, l3);
                Ph[mt][kt][half * 2 + 0] = ((uint32_t)*(uint16_t*)&h1 << 16) | *(uint16_t*)&h0;
                Ph[mt][kt][half * 2 + 1] = ((uint32_t)*(uint16_t*)&h3 << 16) | *(uint16_t*)&h2;
                Pl[mt][kt][half * 2 + 0] = ((uint32_t)*(uint16_t*)&l1 << 16) | *(uint16_t*)&l0;
                Pl[mt][kt][half * 2 + 1] = ((uint32_t)*(uint16_t*)&l3 << 16) | *(uint16_t*)&l2;
            }
        }
    }

    // ---- Phase 4: O = P V via ldmatrix.trans on row-layout V (3-term) ----
    float pacc[2][4][4];
    #pragma unroll
    for (int i = 0; i < 2; i++)
        #pragma unroll
        for (int j = 0; j < 4; j++)
            #pragma unroll
            for (int k = 0; k < 4; k++) pacc[i][j][k] = 0.f;

    // trans lane map reproducing the old Vt fragment:
    //   lanes 0-7: j+0, d+0 | 8-15: j+8, d+0 | 16-23: j+0, d+16B | 24-31: j+8, d+16B
    const int vjOff = ((lane >> 3) & 1) * 8 + (lane & 7);
    const int vdOff = ((lane >> 4) & 1) * 16;

    #pragma unroll
    for (int kt = 0; kt < 8; kt++) {
        #pragma unroll
        for (int p2 = 0; p2 < 2; p2++) {
            uint32_t vo = (uint32_t)((kt * 16 + vjOff) * 80 + p2 * 32 + vdOff);
            uint32_t vh[4], vl[4];
            LDSM_X4_T(vh, sb + AT_VH + vo);
            LDSM_X4_T(vl, sb + AT_VL + vo);
            #pragma unroll
            for (int t2 = 0; t2 < 2; t2++) {
                int nt = p2 * 2 + t2;
                #pragma unroll
                for (int mt = 0; mt < 2; mt++) {
                    mma16816(pacc[mt][nt], Ph[mt][kt], &vh[t2 * 2]);
                    mma16816(pacc[mt][nt], Ph[mt][kt], &vl[t2 * 2]);
                    mma16816(pacc[mt][nt], Pl[mt][kt], &vh[t2 * 2]);
                }
            }
        }
    }

    // ---- Phase 5: epilogue (divide by row sum, store bf16 hi/lo) ----
    #pragma unroll
    for (int mt = 0; mt < 2; mt++) {
        float r0 = 1.f / rsum[mt][0];
        float r1 = 1.f / rsum[mt][1];
        int row0 = rowBase + wm * 32 + mt * 16 + (lane >> 2);
        #pragma unroll
        for (int nt = 0; nt < 4; nt++) {
            int col = hd * HD + nt * 8 + 2 * (lane & 3);
            float v0 = pacc[mt][nt][0] * r0, v1 = pacc[mt][nt][1] * r0;
            float v2 = pacc[mt][nt][2] * r1, v3 = pacc[mt][nt][3] * r1;
            __nv_bfloat16 h0, l0, h1, l1, h2, l2, h3, l3;
            bf16_split(v0, h0, l0); bf16_split(v1, h1, l1);
            bf16_split(v2, h2, l2); bf16_split(v3, h3, l3);
            size_t base0 = (size_t)row0 * DD + col;
            size_t base1 = (size_t)(row0 + 8) * DD + col;
            *(uint32_t*)((char*)oh + base0 * 2) = ((uint32_t)*(uint16_t*)&h1 << 16) | *(uint16_t*)&h0;
            *(uint32_t*)((char*)ol + base0 * 2) = ((uint32_t)*(uint16_t*)&l1 << 16) | *(uint16_t*)&l0;
            *(uint32_t*)((char*)oh + base1 * 2) = ((uint32_t)*(uint16_t*)&h3 << 16) | *(uint16_t*)&h2;
            *(uint32_t*)((char*)ol + base1 * 2) = ((uint32_t)*(uint16_t*)&l3 << 16) | *(uint16_t*)&l2;
        }
    }
}

// ===========================================================================
extern "C" void kernel_launch(void* const* d_in, const int* in_sizes, int n_in,
                              void* d_out, int out_size)
{
    const float* pair_act = nullptr;
    const unsigned char* pair_mask = nullptr;
    const float* ln_gamma = nullptr;
    const float* ln_beta  = nullptr;
    const float* Wqkv = nullptr;
    const float* Wout = nullptr;

    for (int i = 0; i < n_in; i++) {
        int sz = in_sizes[i];
        if      (sz == 8388608) pair_act  = (const float*)d_in[i];
        else if (sz == 32768)   pair_mask = (const unsigned char*)d_in[i];
        else if (sz == 196608)  Wqkv      = (const float*)d_in[i];
        else if (sz == 65536)   Wout      = (const float*)d_in[i];
        else if (sz == 256) {
            if (!ln_gamma) ln_gamma = (const float*)d_in[i];
            else           ln_beta  = (const float*)d_in[i];
        }
    }

    float* out = (float*)d_out;

    void *pxh, *pxl, *pqh, *pql, *path, *patl, *pwqh, *pwql, *pwoh, *pwol;
    cudaGetSymbolAddress(&pxh,  g_x_hi);
    cudaGetSymbolAddress(&pxl,  g_x_lo);
    cudaGetSymbolAddress(&pqh,  g_qkv_hi);
    cudaGetSymbolAddress(&pql,  g_qkv_lo);
    cudaGetSymbolAddress(&path, g_att_hi);
    cudaGetSymbolAddress(&patl, g_att_lo);
    cudaGetSymbolAddress(&pwqh, g_wq_hi);
    cudaGetSymbolAddress(&pwql, g_wq_lo);
    cudaGetSymbolAddress(&pwoh, g_wo_hi);
    cudaGetSymbolAddress(&pwol, g_wo_lo);

    cudaFuncSetAttribute(gemm_bf16_kernel<QKVN, 1>,
                         cudaFuncAttributeMaxDynamicSharedMemorySize, GEMM_SMEM);
    cudaFuncSetAttribute(gemm_bf16_kernel<DD, 0>,
                         cudaFuncAttributeMaxDynamicSharedMemorySize, GEMM_SMEM);
    cudaFuncSetAttribute(attn_kernel,
                         cudaFuncAttributeMaxDynamicSharedMemorySize, ATT_SMEM);

    detect_mask_kernel<<<1, 256>>>(pair_mask);
    conv_mask_kernel<<<128, 256>>>(pair_mask);

    convw_kernel<<<(QKVN * DD + 255) / 256, 256>>>(
        Wqkv, QKVN * DD, (__nv_bfloat16*)pwqh, (__nv_bfloat16*)pwql);
    convw_kernel<<<(DD * DD + 255) / 256, 256>>>(
        Wout, DD * DD, (__nv_bfloat16*)pwoh, (__nv_bfloat16*)pwol);

    ln_kernel<<<MTOT, 256>>>(pair_act, ln_gamma, ln_beta,
                             (__nv_bfloat16*)pxh, (__nv_bfloat16*)pxl);

    gemm_bf16_kernel<QKVN, 1><<<dim3(QKVN / 128, MTOT / 128), 256, GEMM_SMEM>>>(
        (const __nv_bfloat16*)pxh, (const __nv_bfloat16*)pxl,
        (const __nv_bfloat16*)pwqh, (const __nv_bfloat16*)pwql,
        nullptr, (__nv_bfloat16*)pqh, (__nv_bfloat16*)pql);

    attn_kernel<<<dim3(NH, SS, BB), 128, ATT_SMEM>>>(
        (const __nv_bfloat16*)pqh, (const __nv_bfloat16*)pql,
        (__nv_bfloat16*)path, (__nv_bfloat16*)patl);

    gemm_bf16_kernel<DD, 0><<<dim3(DD / 128, MTOT / 128), 256, GEMM_SMEM>>>(
        (const __nv_bfloat16*)path, (const __nv_bfloat16*)patl,
        (const __nv_bfloat16*)pwoh, (const __nv_bfloat16*)pwol,
        out, nullptr, nullptr);
}

// round 10
// speedup vs baseline: 3.6759x; 1.1678x over previous
#include <cuda_runtime.h>
#include <cuda_fp16.h>
#include <cstdint>
#include <math.h>

// Problem constants
#define BB 2
#define SS 128
#define DD 256
#define NH 8
#define HD 32
#define MTOT (BB*SS*SS)      // 32768 rows
#define QKVN 768
#define SCALE 0.17677669529663687f

// Scratch (allocation-free rule: __device__ globals)
__device__ __half g_x[MTOT * DD];
__device__ __half g_qkv[MTOT * QKVN];
__device__ __half g_att[MTOT * DD];
__device__ __half g_wq[QKVN * DD];
__device__ __half g_wo[DD * DD];
__device__ unsigned char g_mask[32768];
__device__ int g_mask_kind;

// ===========================================================================
// Helpers
// ===========================================================================
__device__ __forceinline__ uint32_t smem_u32(const void* p) {
    uint32_t a;
    asm("{ .reg .u64 t; cvta.to.shared.u64 t, %1; cvt.u32.u64 %0, t; }" : "=r"(a) : "l"(p));
    return a;
}
__device__ __forceinline__ uint32_t swz(uint32_t o) {       // SW128 swizzle
    return o ^ ((o >> 3) & 0x70);
}
__device__ __forceinline__ uint32_t packh2(float a, float b) {
    __half2 t = __floats2half2_rn(a, b);
    return *(uint32_t*)&t;
}
__device__ __forceinline__ void mma16816(float* c, const uint32_t* a, const uint32_t* b) {
    asm volatile("mma.sync.aligned.m16n8k16.row.col.f32.f16.f16.f32 "
        "{%0,%1,%2,%3}, {%4,%5,%6,%7}, {%8,%9}, {%0,%1,%2,%3};"
        : "+f"(c[0]), "+f"(c[1]), "+f"(c[2]), "+f"(c[3])
        : "r"(a[0]), "r"(a[1]), "r"(a[2]), "r"(a[3]), "r"(b[0]), "r"(b[1]));
}
#define LDSM_X4(r, addr) \
    asm volatile("ldmatrix.sync.aligned.m8n8.x4.shared.b16 {%0,%1,%2,%3}, [%4];" \
        : "=r"((r)[0]), "=r"((r)[1]), "=r"((r)[2]), "=r"((r)[3]) : "r"(addr))
#define LDSM_X4_T(r, addr) \
    asm volatile("ldmatrix.sync.aligned.m8n8.x4.trans.shared.b16 {%0,%1,%2,%3}, [%4];" \
        : "=r"((r)[0]), "=r"((r)[1]), "=r"((r)[2]), "=r"((r)[3]) : "r"(addr))
__device__ __forceinline__ void cpa16(uint32_t s, const void* g) {
    asm volatile("cp.async.cg.shared.global [%0], [%1], 16;" :: "r"(s), "l"(g));
}
#define CPA_COMMIT() asm volatile("cp.async.commit_group;" ::: "memory")
#define CPA_WAIT0() asm volatile("cp.async.wait_group 0;" ::: "memory")
#define CPA_WAIT1() asm volatile("cp.async.wait_group 1;" ::: "memory")

// ===========================================================================
// Mask normalization (dtype-sniffing)
// ===========================================================================
__global__ __launch_bounds__(256)
void detect_mask_kernel(const unsigned char* __restrict__ m)
{
    __shared__ int fa, fb;
    if (threadIdx.x == 0) { fa = 0; fb = 0; }
    __syncthreads();
    for (int i = threadIdx.x; i < 32768; i += 256) {
        unsigned char v = m[i];
        if (v) { int r = i & 3; if (r == 1) fa = 1; else if (r == 0) fb = 1; }
    }
    __syncthreads();
    if (threadIdx.x == 0) g_mask_kind = fa ? 0 : (fb ? 1 : 2);
}

__global__ __launch_bounds__(256)
void conv_mask_kernel(const unsigned char* __restrict__ m)
{
    int i = blockIdx.x * 256 + threadIdx.x;
    int kind = g_mask_kind;
    unsigned char v;
    if (kind == 0)      v = m[i] ? 1 : 0;
    else if (kind == 1) v = ((const int*)m)[i] ? 1 : 0;
    else                v = (((const float*)m)[i] != 0.f) ? 1 : 0;
    g_mask[i] = v;
}

// ===========================================================================
// Weight conversion: fp32 -> fp16
// ===========================================================================
__global__ __launch_bounds__(256)
void convw_kernel(const float* __restrict__ w, int n, __half* __restrict__ o)
{
    int i = blockIdx.x * 256 + threadIdx.x;
    if (i < n) o[i] = __float2half_rn(w[i]);
}

// ===========================================================================
// LayerNorm: one block per row of 256; writes fp16
// ===========================================================================
__global__ __launch_bounds__(256)
void ln_kernel(const float* __restrict__ in,
               const float* __restrict__ gamma,
               const float* __restrict__ beta,
               __half* __restrict__ o)
{
    int row = blockIdx.x;
    int t = threadIdx.x;
    float v = in[(size_t)row * DD + t];
    float s = v, s2 = v * v;
    #pragma unroll
    for (int of = 16; of > 0; of >>= 1) {
        s  += __shfl_xor_sync(0xffffffffu, s,  of);
        s2 += __shfl_xor_sync(0xffffffffu, s2, of);
    }
    __shared__ float ws[8], ws2[8];
    int w = t >> 5, l = t & 31;
    if (l == 0) { ws[w] = s; ws2[w] = s2; }
    __syncthreads();
    float tot = 0.f, tot2 = 0.f;
    #pragma unroll
    for (int i = 0; i < 8; i++) { tot += ws[i]; tot2 += ws2[i]; }
    float mu  = tot * (1.f / 256.f);
    float var = tot2 * (1.f / 256.f) - mu * mu;
    float r   = rsqrtf(var + 1e-5f);
    o[(size_t)row * DD + t] = __float2half_rn((v - mu) * r * gamma[t] + beta[t]);
}

// ===========================================================================
// fp16 single-pass NT GEMM via mma.sync, cp.async double-buffered.
// BM=128, BN=128, BK=64; 256 threads = warps 4(m) x 2(n); warp tile 32x64.
// MODE 0: fp32 output. MODE 1 (QKV): fused rotary + q-scale, fp16 output.
// ===========================================================================
#define OFF_A 0
#define OFF_B 16384
#define STAGE_SZ 32768
#define GEMM_SMEM (2*STAGE_SZ + 1024)

template<int N, int MODE>
__global__ void __launch_bounds__(256)
gemm_fp16_kernel(const __half* __restrict__ A,
                 const __half* __restrict__ B,
                 float* __restrict__ C,
                 __half* __restrict__ Ch)
{
    extern __shared__ char smem_raw[];
    char* smem = (char*)(((uintptr_t)smem_raw + 1023) & ~(uintptr_t)1023);
    uint32_t sb = smem_u32(smem);

    const int tid = threadIdx.x;
    const int lane = tid & 31;
    const int wid = tid >> 5;
    const int wm = wid & 3;
    const int wn = wid >> 2;
    const int m0 = blockIdx.y * 128;
    const int n0 = blockIdx.x * 128;

    float acc[2][8][4];
    #pragma unroll
    for (int i = 0; i < 2; i++)
        #pragma unroll
        for (int j = 0; j < 8; j++)
            #pragma unroll
            for (int k = 0; k < 4; k++) acc[i][j][k] = 0.f;

    const int aRow = (lane & 15);
    const int aHalf = (lane >> 4) * 16;
    const int bRow = ((lane >> 4) << 3) + (lane & 7);
    const int bHalf = ((lane >> 3) & 1) * 16;

    const int ldRow = tid >> 3;
    const int ldCs  = tid & 7;

    auto load_chunk = [&](int chunk, int buf) {
        int k0 = chunk * 64;
        uint32_t stage = sb + (uint32_t)buf * STAGE_SZ;
        #pragma unroll
        for (int s = 0; s < 4; s++) {
            int row = s * 32 + ldRow;
            uint32_t so = swz((uint32_t)(row * 128 + ldCs * 16));
            cpa16(stage + OFF_A + so, A + (size_t)(m0 + row) * 256 + k0 + ldCs * 8);
            cpa16(stage + OFF_B + so, B + (size_t)(n0 + row) * 256 + k0 + ldCs * 8);
        }
        CPA_COMMIT();
    };

    load_chunk(0, 0);

    for (int chunk = 0; chunk < 4; chunk++) {
        if (chunk < 3) {
            load_chunk(chunk + 1, (chunk + 1) & 1);
            CPA_WAIT1();
        } else {
            CPA_WAIT0();
        }
        __syncthreads();

        uint32_t stage = sb + (uint32_t)(chunk & 1) * STAGE_SZ;
        #pragma unroll
        for (int kk = 0; kk < 4; kk++) {
            int kb = kk * 32;
            uint32_t a[2][4];
            #pragma unroll
            for (int mt = 0; mt < 2; mt++) {
                uint32_t o = swz((uint32_t)((wm * 32 + mt * 16 + aRow) * 128 + kb + aHalf));
                LDSM_X4(a[mt], stage + OFF_A + o);
            }
            #pragma unroll
            for (int p = 0; p < 4; p++) {
                uint32_t bo = swz((uint32_t)((wn * 64 + p * 16 + bRow) * 128 + kb + bHalf));
                uint32_t bf[4];
                LDSM_X4(bf, stage + OFF_B + bo);
                #pragma unroll
                for (int t2 = 0; t2 < 2; t2++) {
                    int nt = p * 2 + t2;
                    #pragma unroll
                    for (int mt = 0; mt < 2; mt++)
                        mma16816(acc[mt][nt], a[mt], &bf[t2 * 2]);
                }
            }
        }
        __syncthreads();
    }

    #pragma unroll
    for (int mt = 0; mt < 2; mt++) {
        int row0 = m0 + wm * 32 + mt * 16 + (lane >> 2);
        #pragma unroll
        for (int nt = 0; nt < 8; nt++) {
            int colg = n0 + wn * 64 + nt * 8 + (lane & 3) * 2;
            float d0 = acc[mt][nt][0], d1 = acc[mt][nt][1];
            float d2 = acc[mt][nt][2], d3 = acc[mt][nt][3];
            if (MODE == 1) {
                // rotary on q head0 (cols 0..31) and k head0 (cols 256..287)
                if (colg < 32 || (colg >= 256 && colg < 288)) {
                    int p = (colg & 31) >> 1;
                    float invf = __expf(-(float)(p & 7) * 1.1512925464970228f);
                    #pragma unroll
                    for (int rr = 0; rr < 2; rr++) {
                        int m = row0 + rr * 8;
                        int xx = (m >> 7) & 127;
                        int yy = m & 127;
                        float pos  = (p < 8) ? (float)xx : (float)yy;
                        float tpos = (2.f * pos - 127.f) * (1.f / 127.f);
                        float sn, cs;
                        __sincosf(tpos * invf, &sn, &cs);
                        if (rr == 0) {
                            float e0 = d0, e1 = d1;
                            d0 = e0 * cs - e1 * sn;
                            d1 = e1 * cs + e0 * sn;
                        } else {
                            float e0 = d2, e1 = d3;
                            d2 = e0 * cs - e1 * sn;
                            d3 = e1 * cs + e0 * sn;
                        }
                    }
                }
                // scale q columns (scale commutes with rotation)
                if (colg < 256) {
                    d0 *= SCALE; d1 *= SCALE; d2 *= SCALE; d3 *= SCALE;
                }
                size_t b0 = (size_t)row0 * N + colg;
                size_t b1 = (size_t)(row0 + 8) * N + colg;
                *(uint32_t*)((char*)Ch + b0 * 2) = packh2(d0, d1);
                *(uint32_t*)((char*)Ch + b1 * 2) = packh2(d2, d3);
            } else {
                *(float2*)&C[(size_t)row0 * N + colg]       = make_float2(d0, d1);
                *(float2*)&C[(size_t)(row0 + 8) * N + colg] = make_float2(d2, d3);
            }
        }
    }
}

// ===========================================================================
// Tensorized attention, fp16 single-pass. One block per (h, x, b); 4 warps.
// qkv arrives fp16 with q pre-scaled and rotary applied.
// V row layout; PV uses ldmatrix.trans. Full softmax in registers.
//   smem rows: 32 fp16 = 64B padded to 80B (conflict-free LDSM).
// ===========================================================================
#define AT_Q 0
#define AT_K 10240
#define AT_V 20480
#define AT_BIAS 30720
#define ATT_SMEM (31232 + 1024)

__global__ void __launch_bounds__(128)
attn_kernel(const __half* __restrict__ qkv,
            __half* __restrict__ oh)
{
    extern __shared__ char smem_raw[];
    char* smem = (char*)(((uintptr_t)smem_raw + 1023) & ~(uintptr_t)1023);
    uint32_t sb = smem_u32(smem);

    const int hd  = blockIdx.x;
    const int xx  = blockIdx.y;
    const int b   = blockIdx.z;
    const int tid = threadIdx.x;
    const int lane = tid & 31;
    const int wm = tid >> 5;
    const int rowBase = b * (SS * SS) + xx * SS;

    // ---- Phase 1: vectorized staging (thread t = row t) ----
    {
        const char* ph = (const char*)(qkv + (size_t)(rowBase + tid) * QKVN + hd * HD);
        #pragma unroll
        for (int g = 0; g < 4; g++) {
            *(uint4*)(smem + AT_Q + tid * 80 + g * 16) = *(const uint4*)(ph + g * 16);
            *(uint4*)(smem + AT_K + tid * 80 + g * 16) = *(const uint4*)(ph + 512 + g * 16);
            *(uint4*)(smem + AT_V + tid * 80 + g * 16) = *(const uint4*)(ph + 1024 + g * 16);
        }
        *(float*)(smem + AT_BIAS + tid * 4) = g_mask[rowBase + tid] ? -1e9f : 0.f;
    }
    __syncthreads();

    const int aRow = (lane & 15);
    const int aHalf = (lane >> 4) * 16;
    const int bRow = ((lane >> 4) << 3) + (lane & 7);
    const int bHalf = ((lane >> 3) & 1) * 16;

    // ---- Phase 2: S = Q K^T ----
    float acc[2][16][4];
    #pragma unroll
    for (int i = 0; i < 2; i++)
        #pragma unroll
        for (int j = 0; j < 16; j++)
            #pragma unroll
            for (int k = 0; k < 4; k++) acc[i][j][k] = 0.f;

    #pragma unroll
    for (int kk = 0; kk < 2; kk++) {
        uint32_t a[2][4];
        #pragma unroll
        for (int mt = 0; mt < 2; mt++) {
            uint32_t o = (uint32_t)((wm * 32 + mt * 16 + aRow) * 80 + kk * 32 + aHalf);
            LDSM_X4(a[mt], sb + AT_Q + o);
        }
        #pragma unroll
        for (int p = 0; p < 8; p++) {
            uint32_t bo = (uint32_t)((p * 16 + bRow) * 80 + kk * 32 + bHalf);
            uint32_t bf[4];
            LDSM_X4(bf, sb + AT_K + bo);
            #pragma unroll
            for (int t2 = 0; t2 < 2; t2++) {
                int nt = p * 2 + t2;
                #pragma unroll
                for (int mt = 0; mt < 2; mt++)
                    mma16816(acc[mt][nt], a[mt], &bf[t2 * 2]);
            }
        }
    }

    // ---- Phase 3: full softmax in registers + P fp16 fragments ----
    uint32_t Ph[2][8][4];
    float rsum[2][2];

    #pragma unroll
    for (int mt = 0; mt < 2; mt++) {
        float mx0 = -3e38f, mx1 = -3e38f;
        #pragma unroll
        for (int nt = 0; nt < 16; nt++) {
            float2 bb = *(float2*)(smem + AT_BIAS + (nt * 8 + 2 * (lane & 3)) * 4);
            acc[mt][nt][0] += bb.x; acc[mt][nt][1] += bb.y;
            acc[mt][nt][2] += bb.x; acc[mt][nt][3] += bb.y;
            mx0 = fmaxf(mx0, fmaxf(acc[mt][nt][0], acc[mt][nt][1]));
            mx1 = fmaxf(mx1, fmaxf(acc[mt][nt][2], acc[mt][nt][3]));
        }
        mx0 = fmaxf(mx0, __shfl_xor_sync(0xffffffffu, mx0, 1));
        mx0 = fmaxf(mx0, __shfl_xor_sync(0xffffffffu, mx0, 2));
        mx1 = fmaxf(mx1, __shfl_xor_sync(0xffffffffu, mx1, 1));
        mx1 = fmaxf(mx1, __shfl_xor_sync(0xffffffffu, mx1, 2));

        float s0 = 0.f, s1 = 0.f;
        #pragma unroll
        for (int nt = 0; nt < 16; nt++) {
            float e0 = __expf(acc[mt][nt][0] - mx0);
            float e1 = __expf(acc[mt][nt][1] - mx0);
            float e2 = __expf(acc[mt][nt][2] - mx1);
            float e3 = __expf(acc[mt][nt][3] - mx1);
            acc[mt][nt][0] = e0; acc[mt][nt][1] = e1;
            acc[mt][nt][2] = e2; acc[mt][nt][3] = e3;
            s0 += e0 + e1; s1 += e2 + e3;
        }
        s0 += __shfl_xor_sync(0xffffffffu, s0, 1);
        s0 += __shfl_xor_sync(0xffffffffu, s0, 2);
        s1 += __shfl_xor_sync(0xffffffffu, s1, 1);
        s1 += __shfl_xor_sync(0xffffffffu, s1, 2);
        rsum[mt][0] = s0; rsum[mt][1] = s1;

        #pragma unroll
        for (int kt = 0; kt < 8; kt++) {
            #pragma unroll
            for (int half = 0; half < 2; half++) {
                const float* c = acc[mt][2 * kt + half];
                Ph[mt][kt][half * 2 + 0] = packh2(c[0], c[1]);
                Ph[mt][kt][half * 2 + 1] = packh2(c[2], c[3]);
            }
        }
    }

    // ---- Phase 4: O = P V via ldmatrix.trans on row-layout V ----
    float pacc[2][4][4];
    #pragma unroll
    for (int i = 0; i < 2; i++)
        #pragma unroll
        for (int j = 0; j < 4; j++)
            #pragma unroll
            for (int k = 0; k < 4; k++) pacc[i][j][k] = 0.f;

    const int vjOff = ((lane >> 3) & 1) * 8 + (lane & 7);
    const int vdOff = ((lane >> 4) & 1) * 16;

    #pragma unroll
    for (int kt = 0; kt < 8; kt++) {
        #pragma unroll
        for (int p2 = 0; p2 < 2; p2++) {
            uint32_t vo = (uint32_t)((kt * 16 + vjOff) * 80 + p2 * 32 + vdOff);
            uint32_t vf[4];
            LDSM_X4_T(vf, sb + AT_V + vo);
            #pragma unroll
            for (int t2 = 0; t2 < 2; t2++) {
                int nt = p2 * 2 + t2;
                #pragma unroll
                for (int mt = 0; mt < 2; mt++)
                    mma16816(pacc[mt][nt], Ph[mt][kt], &vf[t2 * 2]);
            }
        }
    }

    // ---- Phase 5: epilogue (divide by row sum, fp16 store) ----
    #pragma unroll
    for (int mt = 0; mt < 2; mt++) {
        float r0 = 1.f / rsum[mt][0];
        float r1 = 1.f / rsum[mt][1];
        int row0 = rowBase + wm * 32 + mt * 16 + (lane >> 2);
        #pragma unroll
        for (int nt = 0; nt < 4; nt++) {
            int col = hd * HD + nt * 8 + 2 * (lane & 3);
            size_t base0 = (size_t)row0 * DD + col;
            size_t base1 = (size_t)(row0 + 8) * DD + col;
            *(uint32_t*)((char*)oh + base0 * 2) = packh2(pacc[mt][nt][0] * r0, pacc[mt][nt][1] * r0);
            *(uint32_t*)((char*)oh + base1 * 2) = packh2(pacc[mt][nt][2] * r1, pacc[mt][nt][3] * r1);
        }
    }
}

// ===========================================================================
extern "C" void kernel_launch(void* const* d_in, const int* in_sizes, int n_in,
                              void* d_out, int out_size)
{
    const float* pair_act = nullptr;
    const unsigned char* pair_mask = nullptr;
    const float* ln_gamma = nullptr;
    const float* ln_beta  = nullptr;
    const float* Wqkv = nullptr;
    const float* Wout = nullptr;

    for (int i = 0; i < n_in; i++) {
        int sz = in_sizes[i];
        if      (sz == 8388608) pair_act  = (const float*)d_in[i];
        else if (sz == 32768)   pair_mask = (const unsigned char*)d_in[i];
        else if (sz == 196608)  Wqkv      = (const float*)d_in[i];
        else if (sz == 65536)   Wout      = (const float*)d_in[i];
        else if (sz == 256) {
            if (!ln_gamma) ln_gamma = (const float*)d_in[i];
            else           ln_beta  = (const float*)d_in[i];
        }
    }

    float* out = (float*)d_out;

    void *px, *pq, *pat, *pwq, *pwo;
    cudaGetSymbolAddress(&px,  g_x);
    cudaGetSymbolAddress(&pq,  g_qkv);
    cudaGetSymbolAddress(&pat, g_att);
    cudaGetSymbolAddress(&pwq, g_wq);
    cudaGetSymbolAddress(&pwo, g_wo);

    cudaFuncSetAttribute(gemm_fp16_kernel<QKVN, 1>,
                         cudaFuncAttributeMaxDynamicSharedMemorySize, GEMM_SMEM);
    cudaFuncSetAttribute(gemm_fp16_kernel<DD, 0>,
                         cudaFuncAttributeMaxDynamicSharedMemorySize, GEMM_SMEM);
    cudaFuncSetAttribute(attn_kernel,
                         cudaFuncAttributeMaxDynamicSharedMemorySize, ATT_SMEM);

    detect_mask_kernel<<<1, 256>>>(pair_mask);
    conv_mask_kernel<<<128, 256>>>(pair_mask);

    convw_kernel<<<(QKVN * DD + 255) / 256, 256>>>(Wqkv, QKVN * DD, (__half*)pwq);
    convw_kernel<<<(DD * DD + 255) / 256, 256>>>(Wout, DD * DD, (__half*)pwo);

    ln_kernel<<<MTOT, 256>>>(pair_act, ln_gamma, ln_beta, (__half*)px);

    gemm_fp16_kernel<QKVN, 1><<<dim3(QKVN / 128, MTOT / 128), 256, GEMM_SMEM>>>(
        (const __half*)px, (const __half*)pwq, nullptr, (__half*)pq);

    attn_kernel<<<dim3(NH, SS, BB), 128, ATT_SMEM>>>(
        (const __half*)pq, (__half*)pat);

    gemm_fp16_kernel<DD, 0><<<dim3(DD / 128, MTOT / 128), 256, GEMM_SMEM>>>(
        (const __half*)pat, (const __half*)pwo, out, nullptr);
}

// round 11
// speedup vs baseline: 5.5937x; 1.5217x over previous
#include <cuda_runtime.h>
#include <cuda_fp16.h>
#include <cstdint>
#include <math.h>

// Problem constants
#define BB 2
#define SS 128
#define DD 256
#define NH 8
#define HD 32
#define MTOT (BB*SS*SS)      // 32768 rows
#define QKVN 768
#define SCALE 0.17677669529663687f

// Scratch (allocation-free rule: __device__ globals)
__device__ __half g_x[MTOT * DD];
__device__ __half g_qkv[MTOT * QKVN];
__device__ __half g_att[MTOT * DD];
__device__ __half g_wq[QKVN * DD];
__device__ __half g_wo[DD * DD];
__device__ unsigned char g_mask[32768];

// ===========================================================================
// Helpers
// ===========================================================================
__device__ __forceinline__ uint32_t smem_u32(const void* p) {
    uint32_t a;
    asm("{ .reg .u64 t; cvta.to.shared.u64 t, %1; cvt.u32.u64 %0, t; }" : "=r"(a) : "l"(p));
    return a;
}
__device__ __forceinline__ uint32_t swz(uint32_t o) {       // SW128 swizzle
    return o ^ ((o >> 3) & 0x70);
}
__device__ __forceinline__ uint32_t packh2(float a, float b) {
    __half2 t = __floats2half2_rn(a, b);
    return *(uint32_t*)&t;
}
__device__ __forceinline__ void mma16816(float* c, const uint32_t* a, const uint32_t* b) {
    asm volatile("mma.sync.aligned.m16n8k16.row.col.f32.f16.f16.f32 "
        "{%0,%1,%2,%3}, {%4,%5,%6,%7}, {%8,%9}, {%0,%1,%2,%3};"
        : "+f"(c[0]), "+f"(c[1]), "+f"(c[2]), "+f"(c[3])
        : "r"(a[0]), "r"(a[1]), "r"(a[2]), "r"(a[3]), "r"(b[0]), "r"(b[1]));
}
#define LDSM_X4(r, addr) \
    asm volatile("ldmatrix.sync.aligned.m8n8.x4.shared.b16 {%0,%1,%2,%3}, [%4];" \
        : "=r"((r)[0]), "=r"((r)[1]), "=r"((r)[2]), "=r"((r)[3]) : "r"(addr))
#define LDSM_X4_T(r, addr) \
    asm volatile("ldmatrix.sync.aligned.m8n8.x4.trans.shared.b16 {%0,%1,%2,%3}, [%4];" \
        : "=r"((r)[0]), "=r"((r)[1]), "=r"((r)[2]), "=r"((r)[3]) : "r"(addr))
__device__ __forceinline__ void cpa16(uint32_t s, const void* g) {
    asm volatile("cp.async.cg.shared.global [%0], [%1], 16;" :: "r"(s), "l"(g));
}
#define CPA_COMMIT() asm volatile("cp.async.commit_group;" ::: "memory")
#define CPA_WAIT0() asm volatile("cp.async.wait_group 0;" ::: "memory")
#define CPA_WAIT1() asm volatile("cp.async.wait_group 1;" ::: "memory")

// ===========================================================================
// Weight conversion: both matrices in one launch (fp32 -> fp16)
// ===========================================================================
__global__ __launch_bounds__(256)
void convw_all_kernel(const float* __restrict__ wq, const float* __restrict__ wo,
                      __half* __restrict__ oq, __half* __restrict__ oo)
{
    int i = blockIdx.x * 256 + threadIdx.x;        // 0 .. 262143
    if (i < QKVN * DD) {
        oq[i] = __float2half_rn(wq[i]);
    } else {
        int j = i - QKVN * DD;
        oo[j] = __float2half_rn(wo[j]);
    }
}

// ===========================================================================
// Mask: fused dtype-sniff (per-block redundant scan) + normalize.
// uint8 mask: nonzero bytes at off%4==1; int32 0/1: only %4==0;
// float32 0/1 (00 00 80 3f): only %4 in {2,3}.
// ===========================================================================
__global__ __launch_bounds__(256)
void mask_all_kernel(const unsigned char* __restrict__ m)
{
    __shared__ int fa, fb;
    if (threadIdx.x == 0) { fa = 0; fb = 0; }
    __syncthreads();
    for (int i = threadIdx.x * 4; i < 32768; i += 256 * 4) {
        uint32_t w = *(const uint32_t*)(m + i);
        if (w) {
            if (w & 0x0000ff00u) fa = 1;   // byte at %4==1
            if (w & 0x000000ffu) fb = 1;   // byte at %4==0
        }
    }
    __syncthreads();
    int kind = fa ? 0 : (fb ? 1 : 2);
    int i = blockIdx.x * 256 + threadIdx.x;
    unsigned char v;
    if (kind == 0)      v = m[i] ? 1 : 0;
    else if (kind == 1) v = ((const int*)m)[i] ? 1 : 0;
    else                v = (((const float*)m)[i] != 0.f) ? 1 : 0;
    g_mask[i] = v;
}

// ===========================================================================
// LayerNorm: warp per row (8 rows/block), pure shfl reduction, fp16 out
// ===========================================================================
__global__ __launch_bounds__(256)
void ln_kernel(const float* __restrict__ in,
               const float* __restrict__ gamma,
               const float* __restrict__ beta,
               __half* __restrict__ o)
{
    int warp = threadIdx.x >> 5, lane = threadIdx.x & 31;
    int row = blockIdx.x * 8 + warp;
    const float* p = in + (size_t)row * DD + lane * 8;
    float4 a = *(const float4*)p;
    float4 b = *(const float4*)(p + 4);
    float s  = a.x + a.y + a.z + a.w + b.x + b.y + b.z + b.w;
    float s2 = a.x*a.x + a.y*a.y + a.z*a.z + a.w*a.w
             + b.x*b.x + b.y*b.y + b.z*b.z + b.w*b.w;
    #pragma unroll
    for (int of = 16; of > 0; of >>= 1) {
        s  += __shfl_xor_sync(0xffffffffu, s,  of);
        s2 += __shfl_xor_sync(0xffffffffu, s2, of);
    }
    float mu  = s * (1.f / 256.f);
    float var = s2 * (1.f / 256.f) - mu * mu;
    float r   = rsqrtf(var + 1e-5f);
    float4 g0 = *(const float4*)(gamma + lane * 8);
    float4 g1 = *(const float4*)(gamma + lane * 8 + 4);
    float4 t0 = *(const float4*)(beta + lane * 8);
    float4 t1 = *(const float4*)(beta + lane * 8 + 4);
    uint4 outv;
    outv.x = packh2((a.x - mu) * r * g0.x + t0.x, (a.y - mu) * r * g0.y + t0.y);
    outv.y = packh2((a.z - mu) * r * g0.z + t0.z, (a.w - mu) * r * g0.w + t0.w);
    outv.z = packh2((b.x - mu) * r * g1.x + t1.x, (b.y - mu) * r * g1.y + t1.y);
    outv.w = packh2((b.z - mu) * r * g1.z + t1.z, (b.w - mu) * r * g1.w + t1.w);
    *(uint4*)(o + (size_t)row * DD + lane * 8) = outv;
}

// ===========================================================================
// fp16 single-pass NT GEMM via mma.sync, cp.async double-buffered.
// BM=128, BN=128, BK=64; 256 threads = warps 4(m) x 2(n); warp tile 32x64.
// MODE 0: fp32 output. MODE 1 (QKV): fused rotary + q-scale, fp16 output.
// ===========================================================================
#define OFF_A 0
#define OFF_B 16384
#define STAGE_SZ 32768
#define GEMM_SMEM (2*STAGE_SZ + 1024)

template<int N, int MODE>
__global__ void __launch_bounds__(256)
gemm_fp16_kernel(const __half* __restrict__ A,
                 const __half* __restrict__ B,
                 float* __restrict__ C,
                 __half* __restrict__ Ch)
{
    extern __shared__ char smem_raw[];
    char* smem = (char*)(((uintptr_t)smem_raw + 1023) & ~(uintptr_t)1023);
    uint32_t sb = smem_u32(smem);

    const int tid = threadIdx.x;
    const int lane = tid & 31;
    const int wid = tid >> 5;
    const int wm = wid & 3;
    const int wn = wid >> 2;
    const int m0 = blockIdx.y * 128;
    const int n0 = blockIdx.x * 128;

    float acc[2][8][4];
    #pragma unroll
    for (int i = 0; i < 2; i++)
        #pragma unroll
        for (int j = 0; j < 8; j++)
            #pragma unroll
            for (int k = 0; k < 4; k++) acc[i][j][k] = 0.f;

    const int aRow = (lane & 15);
    const int aHalf = (lane >> 4) * 16;
    const int bRow = ((lane >> 4) << 3) + (lane & 7);
    const int bHalf = ((lane >> 3) & 1) * 16;

    const int ldRow = tid >> 3;
    const int ldCs  = tid & 7;

    auto load_chunk = [&](int chunk, int buf) {
        int k0 = chunk * 64;
        uint32_t stage = sb + (uint32_t)buf * STAGE_SZ;
        #pragma unroll
        for (int s = 0; s < 4; s++) {
            int row = s * 32 + ldRow;
            uint32_t so = swz((uint32_t)(row * 128 + ldCs * 16));
            cpa16(stage + OFF_A + so, A + (size_t)(m0 + row) * 256 + k0 + ldCs * 8);
            cpa16(stage + OFF_B + so, B + (size_t)(n0 + row) * 256 + k0 + ldCs * 8);
        }
        CPA_COMMIT();
    };

    load_chunk(0, 0);

    for (int chunk = 0; chunk < 4; chunk++) {
        if (chunk < 3) {
            load_chunk(chunk + 1, (chunk + 1) & 1);
            CPA_WAIT1();
        } else {
            CPA_WAIT0();
        }
        __syncthreads();

        uint32_t stage = sb + (uint32_t)(chunk & 1) * STAGE_SZ;
        #pragma unroll
        for (int kk = 0; kk < 4; kk++) {
            int kb = kk * 32;
            uint32_t a[2][4];
            #pragma unroll
            for (int mt = 0; mt < 2; mt++) {
                uint32_t o = swz((uint32_t)((wm * 32 + mt * 16 + aRow) * 128 + kb + aHalf));
                LDSM_X4(a[mt], stage + OFF_A + o);
            }
            #pragma unroll
            for (int p = 0; p < 4; p++) {
                uint32_t bo = swz((uint32_t)((wn * 64 + p * 16 + bRow) * 128 + kb + bHalf));
                uint32_t bf[4];
                LDSM_X4(bf, stage + OFF_B + bo);
                #pragma unroll
                for (int t2 = 0; t2 < 2; t2++) {
                    int nt = p * 2 + t2;
                    #pragma unroll
                    for (int mt = 0; mt < 2; mt++)
                        mma16816(acc[mt][nt], a[mt], &bf[t2 * 2]);
                }
            }
        }
        __syncthreads();
    }

    #pragma unroll
    for (int mt = 0; mt < 2; mt++) {
        int row0 = m0 + wm * 32 + mt * 16 + (lane >> 2);
        #pragma unroll
        for (int nt = 0; nt < 8; nt++) {
            int colg = n0 + wn * 64 + nt * 8 + (lane & 3) * 2;
            float d0 = acc[mt][nt][0], d1 = acc[mt][nt][1];
            float d2 = acc[mt][nt][2], d3 = acc[mt][nt][3];
            if (MODE == 1) {
                // rotary on q head0 (cols 0..31) and k head0 (cols 256..287)
                if (colg < 32 || (colg >= 256 && colg < 288)) {
                    int p = (colg & 31) >> 1;
                    float invf = __expf(-(float)(p & 7) * 1.1512925464970228f);
                    #pragma unroll
                    for (int rr = 0; rr < 2; rr++) {
                        int m = row0 + rr * 8;
                        int xx = (m >> 7) & 127;
                        int yy = m & 127;
                        float pos  = (p < 8) ? (float)xx : (float)yy;
                        float tpos = (2.f * pos - 127.f) * (1.f / 127.f);
                        float sn, cs;
                        __sincosf(tpos * invf, &sn, &cs);
                        if (rr == 0) {
                            float e0 = d0, e1 = d1;
                            d0 = e0 * cs - e1 * sn;
                            d1 = e1 * cs + e0 * sn;
                        } else {
                            float e0 = d2, e1 = d3;
                            d2 = e0 * cs - e1 * sn;
                            d3 = e1 * cs + e0 * sn;
                        }
                    }
                }
                // scale q columns (scale commutes with rotation)
                if (colg < 256) {
                    d0 *= SCALE; d1 *= SCALE; d2 *= SCALE; d3 *= SCALE;
                }
                size_t b0 = (size_t)row0 * N + colg;
                size_t b1 = (size_t)(row0 + 8) * N + colg;
                *(uint32_t*)((char*)Ch + b0 * 2) = packh2(d0, d1);
                *(uint32_t*)((char*)Ch + b1 * 2) = packh2(d2, d3);
            } else {
                *(float2*)&C[(size_t)row0 * N + colg]       = make_float2(d0, d1);
                *(float2*)&C[(size_t)(row0 + 8) * N + colg] = make_float2(d2, d3);
            }
        }
    }
}

// ===========================================================================
// Tensorized attention, fp16 single-pass. One block per (h, x, b); 4 warps.
// qkv arrives fp16 with q pre-scaled and rotary applied.
// Softmax without max-subtraction (scores are O(1); masked -> exp(-1e9)=0).
// V row layout; PV uses ldmatrix.trans. smem rows padded to 80B.
// ===========================================================================
#define AT_Q 0
#define AT_K 10240
#define AT_V 20480
#define AT_BIAS 30720
#define ATT_SMEM (31232 + 1024)

__global__ void __launch_bounds__(128)
attn_kernel(const __half* __restrict__ qkv,
            __half* __restrict__ oh)
{
    extern __shared__ char smem_raw[];
    char* smem = (char*)(((uintptr_t)smem_raw + 1023) & ~(uintptr_t)1023);
    uint32_t sb = smem_u32(smem);

    const int hd  = blockIdx.x;
    const int xx  = blockIdx.y;
    const int b   = blockIdx.z;
    const int tid = threadIdx.x;
    const int lane = tid & 31;
    const int wm = tid >> 5;
    const int rowBase = b * (SS * SS) + xx * SS;

    // ---- Phase 1: vectorized staging (thread t = row t) ----
    {
        const char* ph = (const char*)(qkv + (size_t)(rowBase + tid) * QKVN + hd * HD);
        #pragma unroll
        for (int g = 0; g < 4; g++) {
            *(uint4*)(smem + AT_Q + tid * 80 + g * 16) = *(const uint4*)(ph + g * 16);
            *(uint4*)(smem + AT_K + tid * 80 + g * 16) = *(const uint4*)(ph + 512 + g * 16);
            *(uint4*)(smem + AT_V + tid * 80 + g * 16) = *(const uint4*)(ph + 1024 + g * 16);
        }
        *(float*)(smem + AT_BIAS + tid * 4) = g_mask[rowBase + tid] ? -1e9f : 0.f;
    }
    __syncthreads();

    const int aRow = (lane & 15);
    const int aHalf = (lane >> 4) * 16;
    const int bRow = ((lane >> 4) << 3) + (lane & 7);
    const int bHalf = ((lane >> 3) & 1) * 16;

    // ---- Phase 2: S = Q K^T ----
    float acc[2][16][4];
    #pragma unroll
    for (int i = 0; i < 2; i++)
        #pragma unroll
        for (int j = 0; j < 16; j++)
            #pragma unroll
            for (int k = 0; k < 4; k++) acc[i][j][k] = 0.f;

    #pragma unroll
    for (int kk = 0; kk < 2; kk++) {
        uint32_t a[2][4];
        #pragma unroll
        for (int mt = 0; mt < 2; mt++) {
            uint32_t o = (uint32_t)((wm * 32 + mt * 16 + aRow) * 80 + kk * 32 + aHalf);
            LDSM_X4(a[mt], sb + AT_Q + o);
        }
        #pragma unroll
        for (int p = 0; p < 8; p++) {
            uint32_t bo = (uint32_t)((p * 16 + bRow) * 80 + kk * 32 + bHalf);
            uint32_t bf[4];
            LDSM_X4(bf, sb + AT_K + bo);
            #pragma unroll
            for (int t2 = 0; t2 < 2; t2++) {
                int nt = p * 2 + t2;
                #pragma unroll
                for (int mt = 0; mt < 2; mt++)
                    mma16816(acc[mt][nt], a[mt], &bf[t2 * 2]);
            }
        }
    }

    // ---- Phase 3: softmax (no max-sub) + P fp16 fragments ----
    uint32_t Ph[2][8][4];
    float rsum[2][2];

    #pragma unroll
    for (int mt = 0; mt < 2; mt++) {
        float s0 = 0.f, s1 = 0.f;
        #pragma unroll
        for (int nt = 0; nt < 16; nt++) {
            float2 bb = *(float2*)(smem + AT_BIAS + (nt * 8 + 2 * (lane & 3)) * 4);
            float e0 = __expf(acc[mt][nt][0] + bb.x);
            float e1 = __expf(acc[mt][nt][1] + bb.y);
            float e2 = __expf(acc[mt][nt][2] + bb.x);
            float e3 = __expf(acc[mt][nt][3] + bb.y);
            acc[mt][nt][0] = e0; acc[mt][nt][1] = e1;
            acc[mt][nt][2] = e2; acc[mt][nt][3] = e3;
            s0 += e0 + e1; s1 += e2 + e3;
        }
        s0 += __shfl_xor_sync(0xffffffffu, s0, 1);
        s0 += __shfl_xor_sync(0xffffffffu, s0, 2);
        s1 += __shfl_xor_sync(0xffffffffu, s1, 1);
        s1 += __shfl_xor_sync(0xffffffffu, s1, 2);
        rsum[mt][0] = s0; rsum[mt][1] = s1;

        #pragma unroll
        for (int kt = 0; kt < 8; kt++) {
            #pragma unroll
            for (int half = 0; half < 2; half++) {
                const float* c = acc[mt][2 * kt + half];
                Ph[mt][kt][half * 2 + 0] = packh2(c[0], c[1]);
                Ph[mt][kt][half * 2 + 1] = packh2(c[2], c[3]);
            }
        }
    }

    // ---- Phase 4: O = P V via ldmatrix.trans on row-layout V ----
    float pacc[2][4][4];
    #pragma unroll
    for (int i = 0; i < 2; i++)
        #pragma unroll
        for (int j = 0; j < 4; j++)
            #pragma unroll
            for (int k = 0; k < 4; k++) pacc[i][j][k] = 0.f;

    const int vjOff = ((lane >> 3) & 1) * 8 + (lane & 7);
    const int vdOff = ((lane >> 4) & 1) * 16;

    #pragma unroll
    for (int kt = 0; kt < 8; kt++) {
        #pragma unroll
        for (int p2 = 0; p2 < 2; p2++) {
            uint32_t vo = (uint32_t)((kt * 16 + vjOff) * 80 + p2 * 32 + vdOff);
            uint32_t vf[4];
            LDSM_X4_T(vf, sb + AT_V + vo);
            #pragma unroll
            for (int t2 = 0; t2 < 2; t2++) {
                int nt = p2 * 2 + t2;
                #pragma unroll
                for (int mt = 0; mt < 2; mt++)
                    mma16816(pacc[mt][nt], Ph[mt][kt], &vf[t2 * 2]);
            }
        }
    }

    // ---- Phase 5: epilogue (divide by row sum, fp16 store) ----
    #pragma unroll
    for (int mt = 0; mt < 2; mt++) {
        float r0 = 1.f / rsum[mt][0];
        float r1 = 1.f / rsum[mt][1];
        int row0 = rowBase + wm * 32 + mt * 16 + (lane >> 2);
        #pragma unroll
        for (int nt = 0; nt < 4; nt++) {
            int col = hd * HD + nt * 8 + 2 * (lane & 3);
            size_t base0 = (size_t)row0 * DD + col;
            size_t base1 = (size_t)(row0 + 8) * DD + col;
            *(uint32_t*)((char*)oh + base0 * 2) = packh2(pacc[mt][nt][0] * r0, pacc[mt][nt][1] * r0);
            *(uint32_t*)((char*)oh + base1 * 2) = packh2(pacc[mt][nt][2] * r1, pacc[mt][nt][3] * r1);
        }
    }
}

// ===========================================================================
extern "C" void kernel_launch(void* const* d_in, const int* in_sizes, int n_in,
                              void* d_out, int out_size)
{
    const float* pair_act = nullptr;
    const unsigned char* pair_mask = nullptr;
    const float* ln_gamma = nullptr;
    const float* ln_beta  = nullptr;
    const float* Wqkv = nullptr;
    const float* Wout = nullptr;

    for (int i = 0; i < n_in; i++) {
        int sz = in_sizes[i];
        if      (sz == 8388608) pair_act  = (const float*)d_in[i];
        else if (sz == 32768)   pair_mask = (const unsigned char*)d_in[i];
        else if (sz == 196608)  Wqkv      = (const float*)d_in[i];
        else if (sz == 65536)   Wout      = (const float*)d_in[i];
        else if (sz == 256) {
            if (!ln_gamma) ln_gamma = (const float*)d_in[i];
            else           ln_beta  = (const float*)d_in[i];
        }
    }

    float* out = (float*)d_out;

    void *px, *pq, *pat, *pwq, *pwo;
    cudaGetSymbolAddress(&px,  g_x);
    cudaGetSymbolAddress(&pq,  g_qkv);
    cudaGetSymbolAddress(&pat, g_att);
    cudaGetSymbolAddress(&pwq, g_wq);
    cudaGetSymbolAddress(&pwo, g_wo);

    cudaFuncSetAttribute(gemm_fp16_kernel<QKVN, 1>,
                         cudaFuncAttributeMaxDynamicSharedMemorySize, GEMM_SMEM);
    cudaFuncSetAttribute(gemm_fp16_kernel<DD, 0>,
                         cudaFuncAttributeMaxDynamicSharedMemorySize, GEMM_SMEM);
    cudaFuncSetAttribute(attn_kernel,
                         cudaFuncAttributeMaxDynamicSharedMemorySize, ATT_SMEM);

    // Launch order chosen so the 4th launch (empirically the ncu capture
    // target) is the QKV GEMM — the dominant kernel we need profiled.
    convw_all_kernel<<<(QKVN * DD + DD * DD + 255) / 256, 256>>>(
        Wqkv, Wout, (__half*)pwq, (__half*)pwo);                       // 0

    ln_kernel<<<MTOT / 8, 256>>>(pair_act, ln_gamma, ln_beta, (__half*)px);  // 1

    mask_all_kernel<<<128, 256>>>(pair_mask);                          // 2

    gemm_fp16_kernel<QKVN, 1><<<dim3(QKVN / 128, MTOT / 128), 256, GEMM_SMEM>>>(
        (const __half*)px, (const __half*)pwq, nullptr, (__half*)pq);  // 3  <- profiled

    attn_kernel<<<dim3(NH, SS, BB), 128, ATT_SMEM>>>(
        (const __half*)pq, (__half*)pat);                              // 4

    gemm_fp16_kernel<DD, 0><<<dim3(DD / 128, MTOT / 128), 256, GEMM_SMEM>>>(
        (const __half*)pat, (const __half*)pwo, out, nullptr);         // 5
}

// round 12
// speedup vs baseline: 9.3161x; 1.6655x over previous
#include <cuda_runtime.h>
#include <cuda_fp16.h>
#include <cstdint>
#include <math.h>

// Problem constants
#define BB 2
#define SS 128
#define DD 256
#define NH 8
#define HD 32
#define MTOT (BB*SS*SS)      // 32768 rows
#define QKVN 768
#define SCALE 0.17677669529663687f

// Scratch (allocation-free rule: __device__ globals)
__device__ __half g_x[MTOT * DD];
__device__ __half g_qkv[MTOT * QKVN];
__device__ __half g_att[MTOT * DD];
__device__ __half g_wq[QKVN * DD];
__device__ __half g_wo[DD * DD];
__device__ unsigned char g_mask[32768];

// ===========================================================================
// Helpers
// ===========================================================================
__device__ __forceinline__ uint32_t smem_u32(const void* p) {
    uint32_t a;
    asm("{ .reg .u64 t; cvta.to.shared.u64 t, %1; cvt.u32.u64 %0, t; }" : "=r"(a) : "l"(p));
    return a;
}
__device__ __forceinline__ uint32_t swz(uint32_t o) {       // SW128 swizzle
    return o ^ ((o >> 3) & 0x70);
}
__device__ __forceinline__ uint32_t packh2(float a, float b) {
    __half2 t = __floats2half2_rn(a, b);
    return *(uint32_t*)&t;
}
__device__ __forceinline__ void mma16816(float* c, const uint32_t* a, const uint32_t* b) {
    asm volatile("mma.sync.aligned.m16n8k16.row.col.f32.f16.f16.f32 "
        "{%0,%1,%2,%3}, {%4,%5,%6,%7}, {%8,%9}, {%0,%1,%2,%3};"
        : "+f"(c[0]), "+f"(c[1]), "+f"(c[2]), "+f"(c[3])
        : "r"(a[0]), "r"(a[1]), "r"(a[2]), "r"(a[3]), "r"(b[0]), "r"(b[1]));
}
#define LDSM_X4(r, addr) \
    asm volatile("ldmatrix.sync.aligned.m8n8.x4.shared.b16 {%0,%1,%2,%3}, [%4];" \
        : "=r"((r)[0]), "=r"((r)[1]), "=r"((r)[2]), "=r"((r)[3]) : "r"(addr))
#define LDSM_X4_T(r, addr) \
    asm volatile("ldmatrix.sync.aligned.m8n8.x4.trans.shared.b16 {%0,%1,%2,%3}, [%4];" \
        : "=r"((r)[0]), "=r"((r)[1]), "=r"((r)[2]), "=r"((r)[3]) : "r"(addr))
__device__ __forceinline__ void cpa16(uint32_t s, const void* g) {
    asm volatile("cp.async.cg.shared.global [%0], [%1], 16;" :: "r"(s), "l"(g));
}
#define CPA_COMMIT() asm volatile("cp.async.commit_group;" ::: "memory")
#define CPA_WAIT0() asm volatile("cp.async.wait_group 0;" ::: "memory")
#define CPA_WAIT1() asm volatile("cp.async.wait_group 1;" ::: "memory")

// ===========================================================================
// Prep: weight fp32->fp16 (blocks 0..1023) + mask sniff/normalize (1024..1151)
// ===========================================================================
__global__ __launch_bounds__(256)
void prep_kernel(const float* __restrict__ wq, const float* __restrict__ wo,
                 const unsigned char* __restrict__ m,
                 __half* __restrict__ oq, __half* __restrict__ oo)
{
    int bid = blockIdx.x;
    if (bid < 1024) {
        int i = bid * 256 + threadIdx.x;        // 0 .. 262143
        if (i < QKVN * DD) {
            oq[i] = __float2half_rn(wq[i]);
        } else {
            int j = i - QKVN * DD;
            oo[j] = __float2half_rn(wo[j]);
        }
    } else {
        // mask dtype sniff (redundant per block, cheap) + normalize.
        // uint8 mask: nonzero bytes at off%4==1; int32 0/1: only %4==0;
        // float32 0/1 (00 00 80 3f): only %4 in {2,3}.
        __shared__ int fa, fb;
        if (threadIdx.x == 0) { fa = 0; fb = 0; }
        __syncthreads();
        for (int i = threadIdx.x * 4; i < 32768; i += 256 * 4) {
            uint32_t w = *(const uint32_t*)(m + i);
            if (w) {
                if (w & 0x0000ff00u) fa = 1;
                if (w & 0x000000ffu) fb = 1;
            }
        }
        __syncthreads();
        int kind = fa ? 0 : (fb ? 1 : 2);
        int i = (bid - 1024) * 256 + threadIdx.x;
        unsigned char v;
        if (kind == 0)      v = m[i] ? 1 : 0;
        else if (kind == 1) v = ((const int*)m)[i] ? 1 : 0;
        else                v = (((const float*)m)[i] != 0.f) ? 1 : 0;
        g_mask[i] = v;
    }
}

// ===========================================================================
// LayerNorm: warp per row (8 rows/block), pure shfl reduction, fp16 out
// ===========================================================================
__global__ __launch_bounds__(256)
void ln_kernel(const float* __restrict__ in,
               const float* __restrict__ gamma,
               const float* __restrict__ beta,
               __half* __restrict__ o)
{
    int warp = threadIdx.x >> 5, lane = threadIdx.x & 31;
    int row = blockIdx.x * 8 + warp;
    const float* p = in + (size_t)row * DD + lane * 8;
    float4 a = *(const float4*)p;
    float4 b = *(const float4*)(p + 4);
    float s  = a.x + a.y + a.z + a.w + b.x + b.y + b.z + b.w;
    float s2 = a.x*a.x + a.y*a.y + a.z*a.z + a.w*a.w
             + b.x*b.x + b.y*b.y + b.z*b.z + b.w*b.w;
    #pragma unroll
    for (int of = 16; of > 0; of >>= 1) {
        s  += __shfl_xor_sync(0xffffffffu, s,  of);
        s2 += __shfl_xor_sync(0xffffffffu, s2, of);
    }
    float mu  = s * (1.f / 256.f);
    float var = s2 * (1.f / 256.f) - mu * mu;
    float r   = rsqrtf(var + 1e-5f);
    float4 g0 = *(const float4*)(gamma + lane * 8);
    float4 g1 = *(const float4*)(gamma + lane * 8 + 4);
    float4 t0 = *(const float4*)(beta + lane * 8);
    float4 t1 = *(const float4*)(beta + lane * 8 + 4);
    uint4 outv;
    outv.x = packh2((a.x - mu) * r * g0.x + t0.x, (a.y - mu) * r * g0.y + t0.y);
    outv.y = packh2((a.z - mu) * r * g0.z + t0.z, (a.w - mu) * r * g0.w + t0.w);
    outv.z = packh2((b.x - mu) * r * g1.x + t1.x, (b.y - mu) * r * g1.y + t1.y);
    outv.w = packh2((b.z - mu) * r * g1.z + t1.z, (b.w - mu) * r * g1.w + t1.w);
    *(uint4*)(o + (size_t)row * DD + lane * 8) = outv;
}

// ===========================================================================
// fp16 single-pass NT GEMM via mma.sync, cp.async double-buffered.
// BM=128, BN=128, BK=64; 256 threads = warps 4(m) x 2(n); warp tile 32x64.
// __launch_bounds__(256, 2): cap regs at 128 so 2 blocks/SM (16 warps).
// MODE 0: fp32 output. MODE 1 (QKV): fused rotary + q-scale, fp16 output.
// ===========================================================================
#define OFF_A 0
#define OFF_B 16384
#define STAGE_SZ 32768
#define GEMM_SMEM (2*STAGE_SZ + 1024)

template<int N, int MODE>
__global__ void __launch_bounds__(256, 2)
gemm_fp16_kernel(const __half* __restrict__ A,
                 const __half* __restrict__ B,
                 float* __restrict__ C,
                 __half* __restrict__ Ch)
{
    extern __shared__ char smem_raw[];
    char* smem = (char*)(((uintptr_t)smem_raw + 1023) & ~(uintptr_t)1023);
    uint32_t sb = smem_u32(smem);

    const int tid = threadIdx.x;
    const int lane = tid & 31;
    const int wid = tid >> 5;
    const int wm = wid & 3;
    const int wn = wid >> 2;
    const int m0 = blockIdx.y * 128;
    const int n0 = blockIdx.x * 128;

    float acc[2][8][4];
    #pragma unroll
    for (int i = 0; i < 2; i++)
        #pragma unroll
        for (int j = 0; j < 8; j++)
            #pragma unroll
            for (int k = 0; k < 4; k++) acc[i][j][k] = 0.f;

    const int aRow = (lane & 15);
    const int aHalf = (lane >> 4) * 16;
    const int bRow = ((lane >> 4) << 3) + (lane & 7);
    const int bHalf = ((lane >> 3) & 1) * 16;

    const int ldRow = tid >> 3;
    const int ldCs  = tid & 7;

    auto load_chunk = [&](int chunk, int buf) {
        int k0 = chunk * 64;
        uint32_t stage = sb + (uint32_t)buf * STAGE_SZ;
        #pragma unroll
        for (int s = 0; s < 4; s++) {
            int row = s * 32 + ldRow;
            uint32_t so = swz((uint32_t)(row * 128 + ldCs * 16));
            cpa16(stage + OFF_A + so, A + (size_t)(m0 + row) * 256 + k0 + ldCs * 8);
            cpa16(stage + OFF_B + so, B + (size_t)(n0 + row) * 256 + k0 + ldCs * 8);
        }
        CPA_COMMIT();
    };

    load_chunk(0, 0);

    for (int chunk = 0; chunk < 4; chunk++) {
        if (chunk < 3) {
            load_chunk(chunk + 1, (chunk + 1) & 1);
            CPA_WAIT1();
        } else {
            CPA_WAIT0();
        }
        __syncthreads();

        uint32_t stage = sb + (uint32_t)(chunk & 1) * STAGE_SZ;
        #pragma unroll
        for (int kk = 0; kk < 4; kk++) {
            int kb = kk * 32;
            uint32_t a[2][4];
            #pragma unroll
            for (int mt = 0; mt < 2; mt++) {
                uint32_t o = swz((uint32_t)((wm * 32 + mt * 16 + aRow) * 128 + kb + aHalf));
                LDSM_X4(a[mt], stage + OFF_A + o);
            }
            #pragma unroll
            for (int p = 0; p < 4; p++) {
                uint32_t bo = swz((uint32_t)((wn * 64 + p * 16 + bRow) * 128 + kb + bHalf));
                uint32_t bf[4];
                LDSM_X4(bf, stage + OFF_B + bo);
                #pragma unroll
                for (int t2 = 0; t2 < 2; t2++) {
                    int nt = p * 2 + t2;
                    #pragma unroll
                    for (int mt = 0; mt < 2; mt++)
                        mma16816(acc[mt][nt], a[mt], &bf[t2 * 2]);
                }
            }
        }
        __syncthreads();
    }

    #pragma unroll
    for (int mt = 0; mt < 2; mt++) {
        int row0 = m0 + wm * 32 + mt * 16 + (lane >> 2);
        #pragma unroll
        for (int nt = 0; nt < 8; nt++) {
            int colg = n0 + wn * 64 + nt * 8 + (lane & 3) * 2;
            float d0 = acc[mt][nt][0], d1 = acc[mt][nt][1];
            float d2 = acc[mt][nt][2], d3 = acc[mt][nt][3];
            if (MODE == 1) {
                // rotary on q head0 (cols 0..31) and k head0 (cols 256..287)
                if (colg < 32 || (colg >= 256 && colg < 288)) {
                    int p = (colg & 31) >> 1;
                    float invf = __expf(-(float)(p & 7) * 1.1512925464970228f);
                    #pragma unroll
                    for (int rr = 0; rr < 2; rr++) {
                        int m = row0 + rr * 8;
                        int xx = (m >> 7) & 127;
                        int yy = m & 127;
                        float pos  = (p < 8) ? (float)xx : (float)yy;
                        float tpos = (2.f * pos - 127.f) * (1.f / 127.f);
                        float sn, cs;
                        __sincosf(tpos * invf, &sn, &cs);
                        if (rr == 0) {
                            float e0 = d0, e1 = d1;
                            d0 = e0 * cs - e1 * sn;
                            d1 = e1 * cs + e0 * sn;
                        } else {
                            float e0 = d2, e1 = d3;
                            d2 = e0 * cs - e1 * sn;
                            d3 = e1 * cs + e0 * sn;
                        }
                    }
                }
                // scale q columns (scale commutes with rotation)
                if (colg < 256) {
                    d0 *= SCALE; d1 *= SCALE; d2 *= SCALE; d3 *= SCALE;
                }
                size_t b0 = (size_t)row0 * N + colg;
                size_t b1 = (size_t)(row0 + 8) * N + colg;
                *(uint32_t*)((char*)Ch + b0 * 2) = packh2(d0, d1);
                *(uint32_t*)((char*)Ch + b1 * 2) = packh2(d2, d3);
            } else {
                *(float2*)&C[(size_t)row0 * N + colg]       = make_float2(d0, d1);
                *(float2*)&C[(size_t)(row0 + 8) * N + colg] = make_float2(d2, d3);
            }
        }
    }
}

// ===========================================================================
// Tensorized attention, fp16 single-pass. One block per (h, x, b); 4 warps.
// qkv arrives fp16 with q pre-scaled and rotary applied.
// Softmax without max-subtraction (scores are O(1); masked -> exp(-1e9)=0).
// V row layout; PV uses ldmatrix.trans. smem rows padded to 80B.
// ===========================================================================
#define AT_Q 0
#define AT_K 10240
#define AT_V 20480
#define AT_BIAS 30720
#define ATT_SMEM (31232 + 1024)

__global__ void __launch_bounds__(128)
attn_kernel(const __half* __restrict__ qkv,
            __half* __restrict__ oh)
{
    extern __shared__ char smem_raw[];
    char* smem = (char*)(((uintptr_t)smem_raw + 1023) & ~(uintptr_t)1023);
    uint32_t sb = smem_u32(smem);

    const int hd  = blockIdx.x;
    const int xx  = blockIdx.y;
    const int b   = blockIdx.z;
    const int tid = threadIdx.x;
    const int lane = tid & 31;
    const int wm = tid >> 5;
    const int rowBase = b * (SS * SS) + xx * SS;

    // ---- Phase 1: vectorized staging (thread t = row t) ----
    {
        const char* ph = (const char*)(qkv + (size_t)(rowBase + tid) * QKVN + hd * HD);
        #pragma unroll
        for (int g = 0; g < 4; g++) {
            *(uint4*)(smem + AT_Q + tid * 80 + g * 16) = *(const uint4*)(ph + g * 16);
            *(uint4*)(smem + AT_K + tid * 80 + g * 16) = *(const uint4*)(ph + 512 + g * 16);
            *(uint4*)(smem + AT_V + tid * 80 + g * 16) = *(const uint4*)(ph + 1024 + g * 16);
        }
        *(float*)(smem + AT_BIAS + tid * 4) = g_mask[rowBase + tid] ? -1e9f : 0.f;
    }
    __syncthreads();

    const int aRow = (lane & 15);
    const int aHalf = (lane >> 4) * 16;
    const int bRow = ((lane >> 4) << 3) + (lane & 7);
    const int bHalf = ((lane >> 3) & 1) * 16;

    // ---- Phase 2: S = Q K^T ----
    float acc[2][16][4];
    #pragma unroll
    for (int i = 0; i < 2; i++)
        #pragma unroll
        for (int j = 0; j < 16; j++)
            #pragma unroll
            for (int k = 0; k < 4; k++) acc[i][j][k] = 0.f;

    #pragma unroll
    for (int kk = 0; kk < 2; kk++) {
        uint32_t a[2][4];
        #pragma unroll
        for (int mt = 0; mt < 2; mt++) {
            uint32_t o = (uint32_t)((wm * 32 + mt * 16 + aRow) * 80 + kk * 32 + aHalf);
            LDSM_X4(a[mt], sb + AT_Q + o);
        }
        #pragma unroll
        for (int p = 0; p < 8; p++) {
            uint32_t bo = (uint32_t)((p * 16 + bRow) * 80 + kk * 32 + bHalf);
            uint32_t bf[4];
            LDSM_X4(bf, sb + AT_K + bo);
            #pragma unroll
            for (int t2 = 0; t2 < 2; t2++) {
                int nt = p * 2 + t2;
                #pragma unroll
                for (int mt = 0; mt < 2; mt++)
                    mma16816(acc[mt][nt], a[mt], &bf[t2 * 2]);
            }
        }
    }

    // ---- Phase 3: softmax (no max-sub) + P fp16 fragments ----
    uint32_t Ph[2][8][4];
    float rsum[2][2];

    #pragma unroll
    for (int mt = 0; mt < 2; mt++) {
        float s0 = 0.f, s1 = 0.f;
        #pragma unroll
        for (int nt = 0; nt < 16; nt++) {
            float2 bb = *(float2*)(smem + AT_BIAS + (nt * 8 + 2 * (lane & 3)) * 4);
            float e0 = __expf(acc[mt][nt][0] + bb.x);
            float e1 = __expf(acc[mt][nt][1] + bb.y);
            float e2 = __expf(acc[mt][nt][2] + bb.x);
            float e3 = __expf(acc[mt][nt][3] + bb.y);
            acc[mt][nt][0] = e0; acc[mt][nt][1] = e1;
            acc[mt][nt][2] = e2; acc[mt][nt][3] = e3;
            s0 += e0 + e1; s1 += e2 + e3;
        }
        s0 += __shfl_xor_sync(0xffffffffu, s0, 1);
        s0 += __shfl_xor_sync(0xffffffffu, s0, 2);
        s1 += __shfl_xor_sync(0xffffffffu, s1, 1);
        s1 += __shfl_xor_sync(0xffffffffu, s1, 2);
        rsum[mt][0] = s0; rsum[mt][1] = s1;

        #pragma unroll
        for (int kt = 0; kt < 8; kt++) {
            #pragma unroll
            for (int half = 0; half < 2; half++) {
                const float* c = acc[mt][2 * kt + half];
                Ph[mt][kt][half * 2 + 0] = packh2(c[0], c[1]);
                Ph[mt][kt][half * 2 + 1] = packh2(c[2], c[3]);
            }
        }
    }

    // ---- Phase 4: O = P V via ldmatrix.trans on row-layout V ----
    float pacc[2][4][4];
    #pragma unroll
    for (int i = 0; i < 2; i++)
        #pragma unroll
        for (int j = 0; j < 4; j++)
            #pragma unroll
            for (int k = 0; k < 4; k++) pacc[i][j][k] = 0.f;

    const int vjOff = ((lane >> 3) & 1) * 8 + (lane & 7);
    const int vdOff = ((lane >> 4) & 1) * 16;

    #pragma unroll
    for (int kt = 0; kt < 8; kt++) {
        #pragma unroll
        for (int p2 = 0; p2 < 2; p2++) {
            uint32_t vo = (uint32_t)((kt * 16 + vjOff) * 80 + p2 * 32 + vdOff);
            uint32_t vf[4];
            LDSM_X4_T(vf, sb + AT_V + vo);
            #pragma unroll
            for (int t2 = 0; t2 < 2; t2++) {
                int nt = p2 * 2 + t2;
                #pragma unroll
                for (int mt = 0; mt < 2; mt++)
                    mma16816(pacc[mt][nt], Ph[mt][kt], &vf[t2 * 2]);
            }
        }
    }

    // ---- Phase 5: epilogue (divide by row sum, fp16 store) ----
    #pragma unroll
    for (int mt = 0; mt < 2; mt++) {
        float r0 = 1.f / rsum[mt][0];
        float r1 = 1.f / rsum[mt][1];
        int row0 = rowBase + wm * 32 + mt * 16 + (lane >> 2);
        #pragma unroll
        for (int nt = 0; nt < 4; nt++) {
            int col = hd * HD + nt * 8 + 2 * (lane & 3);
            size_t base0 = (size_t)row0 * DD + col;
            size_t base1 = (size_t)(row0 + 8) * DD + col;
            *(uint32_t*)((char*)oh + base0 * 2) = packh2(pacc[mt][nt][0] * r0, pacc[mt][nt][1] * r0);
            *(uint32_t*)((char*)oh + base1 * 2) = packh2(pacc[mt][nt][2] * r1, pacc[mt][nt][3] * r1);
        }
    }
}

// ===========================================================================
extern "C" void kernel_launch(void* const* d_in, const int* in_sizes, int n_in,
                              void* d_out, int out_size)
{
    const float* pair_act = nullptr;
    const unsigned char* pair_mask = nullptr;
    const float* ln_gamma = nullptr;
    const float* ln_beta  = nullptr;
    const float* Wqkv = nullptr;
    const float* Wout = nullptr;

    for (int i = 0; i < n_in; i++) {
        int sz = in_sizes[i];
        if      (sz == 8388608) pair_act  = (const float*)d_in[i];
        else if (sz == 32768)   pair_mask = (const unsigned char*)d_in[i];
        else if (sz == 196608)  Wqkv      = (const float*)d_in[i];
        else if (sz == 65536)   Wout      = (const float*)d_in[i];
        else if (sz == 256) {
            if (!ln_gamma) ln_gamma = (const float*)d_in[i];
            else           ln_beta  = (const float*)d_in[i];
        }
    }

    float* out = (float*)d_out;

    void *px, *pq, *pat, *pwq, *pwo;
    cudaGetSymbolAddress(&px,  g_x);
    cudaGetSymbolAddress(&pq,  g_qkv);
    cudaGetSymbolAddress(&pat, g_att);
    cudaGetSymbolAddress(&pwq, g_wq);
    cudaGetSymbolAddress(&pwo, g_wo);

    cudaFuncSetAttribute(gemm_fp16_kernel<QKVN, 1>,
                         cudaFuncAttributeMaxDynamicSharedMemorySize, GEMM_SMEM);
    cudaFuncSetAttribute(gemm_fp16_kernel<DD, 0>,
                         cudaFuncAttributeMaxDynamicSharedMemorySize, GEMM_SMEM);
    cudaFuncSetAttribute(attn_kernel,
                         cudaFuncAttributeMaxDynamicSharedMemorySize, ATT_SMEM);

    // Launch order: 4th launch (index 3, the ncu capture target) = attn.
    prep_kernel<<<1152, 256>>>(Wqkv, Wout, pair_mask,
                               (__half*)pwq, (__half*)pwo);             // 0

    ln_kernel<<<MTOT / 8, 256>>>(pair_act, ln_gamma, ln_beta, (__half*)px);  // 1

    gemm_fp16_kernel<QKVN, 1><<<dim3(QKVN / 128, MTOT / 128), 256, GEMM_SMEM>>>(
        (const __half*)px, (const __half*)pwq, nullptr, (__half*)pq);   // 2

    attn_kernel<<<dim3(NH, SS, BB), 128, ATT_SMEM>>>(
        (const __half*)pq, (__half*)pat);                               // 3  <- profiled

    gemm_fp16_kernel<DD, 0><<<dim3(DD / 128, MTOT / 128), 256, GEMM_SMEM>>>(
        (const __half*)pat, (const __half*)pwo, out, nullptr);          // 4
}